// round 1
// baseline (speedup 1.0000x reference)
#include <cuda_runtime.h>

// ============================================================================
// IntegerCifar10Net — 4-bit quantized CNN, B=512, CIFAR-10.
// Strategy: activations & weights are exact multiples of 1/7 after quant.
// Store activation LEVELS (0..7) packed 4-per-int32 (channel groups of 4),
// weights as LEVELS (-7..7) packed the same way, accumulate exactly with
// __dp4a, apply float epilogue  p = (acc/49)*g + b ; clip ; rint(p*7) ; relu.
// Conv1 (float input) runs in fp32 with pre-quantized float weights.
// ============================================================================

__device__ __forceinline__ int qlev(float w) {
    w = fminf(fmaxf(w, -1.0f), 1.0f);
    return (int)rintf(w * 7.0f);   // round-half-to-even, matches jnp.round
}

__device__ __forceinline__ unsigned bmax4(unsigned a, unsigned b) {
    unsigned r = 0;
#pragma unroll
    for (int i = 0; i < 4; i++) {
        unsigned aa = (a >> (8 * i)) & 0xFFu;
        unsigned bb = (b >> (8 * i)) & 0xFFu;
        r |= (aa > bb ? aa : bb) << (8 * i);
    }
    return r;
}

// ---------------------------------------------------------------------------
// Static scratch (no cudaMalloc allowed)
// ---------------------------------------------------------------------------
__device__ unsigned      g_bufA[512 * 16 * 32 * 32];   // 33.5 MB
__device__ unsigned      g_bufB[512 * 16 * 32 * 32];   // 33.5 MB
__device__ float         g_qw1[64 * 3 * 9];
__device__ int           g_w2[64 * 16 * 9];
__device__ int           g_w3[128 * 16 * 9];
__device__ int           g_w4[128 * 32 * 9];
__device__ int           g_w5[256 * 32 * 9];
__device__ int           g_w6[256 * 64 * 9];
__device__ int           g_wf1[512 * 1024];
__device__ signed char   g_wf2[10 * 512];
__device__ unsigned char g_fc1[512 * 512];

// ---------------------------------------------------------------------------
// Weight prep kernels
// ---------------------------------------------------------------------------
__global__ void quant_w1_k(const float* __restrict__ w, float* __restrict__ qw, int n) {
    int i = blockIdx.x * blockDim.x + threadIdx.x;
    if (i < n) qw[i] = (float)qlev(w[i]) / 7.0f;
}

// conv weights OIHW -> [o][c4][k] int32, bytes = channels 4c4..4c4+3
__global__ void pack_convw_k(const float* __restrict__ w, int* __restrict__ out,
                             int COUT, int CIN) {
    int idx = blockIdx.x * blockDim.x + threadIdx.x;
    int CIN4 = CIN / 4;
    int total = COUT * CIN4 * 9;
    if (idx >= total) return;
    int k  = idx % 9;
    int t  = idx / 9;
    int c4 = t % CIN4;
    int o  = t / CIN4;
    unsigned word = 0;
#pragma unroll
    for (int l = 0; l < 4; l++) {
        int j = qlev(w[(o * CIN + 4 * c4 + l) * 9 + k]);
        word |= (unsigned)(j & 0xFF) << (8 * l);
    }
    out[idx] = (int)word;
}

// wf1 [512][4096] (k = c*16 + y*4 + x) -> [o][m] int32 where m = c4*16 + y*4 + x,
// bytes = channels 4c4..4c4+3 (matches the packed NCHW feature layout).
__global__ void pack_fc1_k(const float* __restrict__ w, int* __restrict__ out) {
    int idx = blockIdx.x * blockDim.x + threadIdx.x;
    if (idx >= 512 * 1024) return;
    int m  = idx % 1024;
    int o  = idx / 1024;
    int c4 = m / 16;
    int r  = m % 16;
    unsigned word = 0;
#pragma unroll
    for (int l = 0; l < 4; l++) {
        int k = (4 * c4 + l) * 16 + r;
        int j = qlev(w[o * 4096 + k]);
        word |= (unsigned)(j & 0xFF) << (8 * l);
    }
    out[idx] = (int)word;
}

__global__ void pack_fc2_k(const float* __restrict__ w, signed char* __restrict__ out) {
    int idx = blockIdx.x * blockDim.x + threadIdx.x;
    if (idx < 10 * 512) out[idx] = (signed char)qlev(w[idx]);
}

// ---------------------------------------------------------------------------
// Conv1: float input (512,3,32,32), fp32 weights, output packed levels
// ---------------------------------------------------------------------------
__global__ void __launch_bounds__(1024)
conv1_kernel(const float* __restrict__ x, const float* __restrict__ qw,
             const float* __restrict__ g, const float* __restrict__ b,
             unsigned* __restrict__ out) {
    __shared__ float s_in[3][34][34];
    __shared__ float s_w[16][27];
    const int tid = threadIdx.x;
    const int oy = tid / 32, ox = tid % 32;
    const int n = blockIdx.y;
    const int oc0 = blockIdx.x * 16;

    for (int i = tid; i < 3 * 34 * 34; i += 1024) {
        int t = i;
        int xx = t % 34; t /= 34;
        int yy = t % 34; t /= 34;
        int c = t;
        int yi = yy - 1, xi = xx - 1;
        float v = 0.0f;
        if ((unsigned)yi < 32u && (unsigned)xi < 32u)
            v = x[((n * 3 + c) * 32 + yi) * 32 + xi];
        s_in[c][yy][xx] = v;
    }
    for (int i = tid; i < 16 * 27; i += 1024)
        s_w[i / 27][i % 27] = qw[(oc0 + i / 27) * 27 + i % 27];
    __syncthreads();

    float acc[16];
#pragma unroll
    for (int o = 0; o < 16; o++) acc[o] = 0.0f;

#pragma unroll
    for (int c = 0; c < 3; c++) {
        float wv[9];
#pragma unroll
        for (int ky = 0; ky < 3; ky++)
#pragma unroll
            for (int kx = 0; kx < 3; kx++)
                wv[ky * 3 + kx] = s_in[c][oy + ky][ox + kx];
#pragma unroll
        for (int o = 0; o < 16; o++) {
            float a = acc[o];
#pragma unroll
            for (int k = 0; k < 9; k++)
                a = fmaf(wv[k], s_w[o][c * 9 + k], a);
            acc[o] = a;
        }
    }

#pragma unroll
    for (int j = 0; j < 4; j++) {
        unsigned word = 0;
#pragma unroll
        for (int l = 0; l < 4; l++) {
            int o = j * 4 + l;
            float p = acc[o] * g[oc0 + o] + b[oc0 + o];
            p = fminf(fmaxf(p, -1.0f), 1.0f);
            int lev = (int)rintf(p * 7.0f);
            lev = max(lev, 0);
            word |= (unsigned)lev << (8 * l);
        }
        out[((n * 16 + (oc0 / 4 + j)) * 32 + oy) * 32 + ox] = word;
    }
}

// ---------------------------------------------------------------------------
// Generic quantized conv (levels in, levels out) with dp4a
//   input layout:  [n][CIN4][H][W]  int32 (char4 channel groups)
//   weight layout: [oc][CIN4][9]    int32
// ---------------------------------------------------------------------------
template <int H, int W, int CIN4, int COUT, int TOC, int CCH, int NB>
__global__ void __launch_bounds__(NB* H* W)
conv_q(const int* __restrict__ in, const int* __restrict__ wq,
       const float* __restrict__ g, const float* __restrict__ b,
       unsigned* __restrict__ out) {
    constexpr int PX = H * W;
    constexpr int NT = NB * PX;
    __shared__ int s_in[NB][CCH][H + 2][W + 2];
    __shared__ int s_w[TOC][CCH][9];

    const int tid = threadIdx.x;
    const int nsub = tid / PX;
    const int px = tid % PX;
    const int oy = px / W, ox = px % W;
    const int n = blockIdx.y * NB + nsub;
    const int oc0 = blockIdx.x * TOC;

    int acc[TOC];
#pragma unroll
    for (int o = 0; o < TOC; o++) acc[o] = 0;

    for (int c0 = 0; c0 < CIN4; c0 += CCH) {
        constexpr int LIN = NB * CCH * (H + 2) * (W + 2);
        for (int i = tid; i < LIN; i += NT) {
            int t = i;
            int xx = t % (W + 2); t /= (W + 2);
            int yy = t % (H + 2); t /= (H + 2);
            int cc = t % CCH;
            int nn = t / CCH;
            int yi = yy - 1, xi = xx - 1;
            int v = 0;
            if ((unsigned)yi < (unsigned)H && (unsigned)xi < (unsigned)W)
                v = in[(((blockIdx.y * NB + nn) * CIN4 + c0 + cc) * H + yi) * W + xi];
            s_in[nn][cc][yy][xx] = v;
        }
        constexpr int LW = TOC * CCH * 9;
        for (int i = tid; i < LW; i += NT) {
            int k = i % 9;
            int t = i / 9;
            int cc = t % CCH;
            int o = t / CCH;
            s_w[o][cc][k] = wq[((oc0 + o) * CIN4 + c0 + cc) * 9 + k];
        }
        __syncthreads();

#pragma unroll 1
        for (int cc = 0; cc < CCH; cc++) {
            int wv[9];
#pragma unroll
            for (int ky = 0; ky < 3; ky++)
#pragma unroll
                for (int kx = 0; kx < 3; kx++)
                    wv[ky * 3 + kx] = s_in[nsub][cc][oy + ky][ox + kx];
#pragma unroll
            for (int o = 0; o < TOC; o++) {
                int a = acc[o];
#pragma unroll
                for (int k = 0; k < 9; k++)
                    a = __dp4a(wv[k], s_w[o][cc][k], a);
                acc[o] = a;
            }
        }
        __syncthreads();
    }

#pragma unroll
    for (int j = 0; j < TOC / 4; j++) {
        unsigned word = 0;
#pragma unroll
        for (int l = 0; l < 4; l++) {
            int o = j * 4 + l;
            float y = (float)acc[o] / 49.0f;
            float p = y * g[oc0 + o] + b[oc0 + o];
            p = fminf(fmaxf(p, -1.0f), 1.0f);
            int lev = (int)rintf(p * 7.0f);
            lev = max(lev, 0);
            word |= (unsigned)lev << (8 * l);
        }
        out[((n * (COUT / 4) + (oc0 / 4 + j)) * H + oy) * W + ox] = word;
    }
}

// ---------------------------------------------------------------------------
// 2x2 maxpool on packed levels (monotone -> pool on levels is exact)
// ---------------------------------------------------------------------------
__global__ void pool_k(const unsigned* __restrict__ in, unsigned* __restrict__ out,
                       int C4, int HO, int total) {
    int idx = blockIdx.x * blockDim.x + threadIdx.x;
    if (idx >= total) return;
    int x = idx % HO;
    int y = (idx / HO) % HO;
    int c = (idx / (HO * HO)) % C4;
    int n = idx / (HO * HO * C4);
    int HI = 2 * HO;
    const unsigned* p = in + (((n * C4 + c) * HI + 2 * y) * HI + 2 * x);
    unsigned m0 = bmax4(p[0], p[1]);
    unsigned m1 = bmax4(p[HI], p[HI + 1]);
    out[idx] = bmax4(m0, m1);
}

// ---------------------------------------------------------------------------
// FC1: [512][1024 words] x [512][1024 words] -> level bytes [512][512]
// ---------------------------------------------------------------------------
__global__ void fc1_kernel(const int* __restrict__ h, const int* __restrict__ w,
                           const float* __restrict__ g, const float* __restrict__ b,
                           unsigned char* __restrict__ out) {
    __shared__ int sa[16][17];
    __shared__ int sw[16][17];
    const int tx = threadIdx.x, ty = threadIdx.y;
    const int n = blockIdx.y * 16 + ty;
    const int o = blockIdx.x * 16 + tx;
    int acc = 0;
    for (int m0 = 0; m0 < 1024; m0 += 16) {
        sa[ty][tx] = h[(blockIdx.y * 16 + ty) * 1024 + m0 + tx];
        sw[ty][tx] = w[(blockIdx.x * 16 + ty) * 1024 + m0 + tx];
        __syncthreads();
#pragma unroll
        for (int mm = 0; mm < 16; mm++)
            acc = __dp4a(sa[ty][mm], sw[tx][mm], acc);
        __syncthreads();
    }
    float y = (float)acc / 49.0f;
    float p = y * g[o] + b[o];
    p = fminf(fmaxf(p, -1.0f), 1.0f);
    int lev = (int)rintf(p * 7.0f);
    lev = max(lev, 0);
    out[n * 512 + o] = (unsigned char)lev;
}

// ---------------------------------------------------------------------------
// FC2: levels [512][512] x [10][512] -> float out [512][10] (qact, no relu)
// ---------------------------------------------------------------------------
__global__ void fc2_kernel(const unsigned char* __restrict__ h,
                           const signed char* __restrict__ w,
                           const float* __restrict__ g, const float* __restrict__ b,
                           float* __restrict__ out) {
    const int n = blockIdx.x;
    const int lane = threadIdx.x;
    for (int o = 0; o < 10; o++) {
        int acc = 0;
        for (int k = lane; k < 512; k += 32)
            acc += (int)h[n * 512 + k] * (int)w[o * 512 + k];
#pragma unroll
        for (int off = 16; off > 0; off >>= 1)
            acc += __shfl_xor_sync(0xFFFFFFFFu, acc, off);
        if (lane == 0) {
            float y = (float)acc / 49.0f;
            float p = y * g[o] + b[o];
            p = fminf(fmaxf(p, -1.0f), 1.0f);
            int lev = (int)rintf(p * 7.0f);
            out[n * 10 + o] = (float)lev / 7.0f;
        }
    }
}

// ---------------------------------------------------------------------------
// Launch
// ---------------------------------------------------------------------------
extern "C" void kernel_launch(void* const* d_in, const int* in_sizes, int n_in,
                              void* d_out, int out_size) {
    const float* x   = (const float*)d_in[0];
    const float* w1  = (const float*)d_in[1];
    const float* g1  = (const float*)d_in[2];
    const float* b1  = (const float*)d_in[3];
    const float* w2  = (const float*)d_in[4];
    const float* g2  = (const float*)d_in[5];
    const float* b2  = (const float*)d_in[6];
    const float* w3  = (const float*)d_in[7];
    const float* g3  = (const float*)d_in[8];
    const float* b3  = (const float*)d_in[9];
    const float* w4  = (const float*)d_in[10];
    const float* g4  = (const float*)d_in[11];
    const float* b4  = (const float*)d_in[12];
    const float* w5  = (const float*)d_in[13];
    const float* g5  = (const float*)d_in[14];
    const float* b5  = (const float*)d_in[15];
    const float* w6  = (const float*)d_in[16];
    const float* g6  = (const float*)d_in[17];
    const float* b6  = (const float*)d_in[18];
    const float* wf1 = (const float*)d_in[19];
    const float* gf1 = (const float*)d_in[20];
    const float* bf1 = (const float*)d_in[21];
    const float* wf2 = (const float*)d_in[22];
    const float* gf2 = (const float*)d_in[23];
    const float* bf2 = (const float*)d_in[24];

    void *bufA, *bufB, *qw1, *w2p, *w3p, *w4p, *w5p, *w6p, *wf1p, *wf2p, *fc1o;
    cudaGetSymbolAddress(&bufA, g_bufA);
    cudaGetSymbolAddress(&bufB, g_bufB);
    cudaGetSymbolAddress(&qw1, g_qw1);
    cudaGetSymbolAddress(&w2p, g_w2);
    cudaGetSymbolAddress(&w3p, g_w3);
    cudaGetSymbolAddress(&w4p, g_w4);
    cudaGetSymbolAddress(&w5p, g_w5);
    cudaGetSymbolAddress(&w6p, g_w6);
    cudaGetSymbolAddress(&wf1p, g_wf1);
    cudaGetSymbolAddress(&wf2p, g_wf2);
    cudaGetSymbolAddress(&fc1o, g_fc1);

    // -------- weight prep --------
    quant_w1_k<<<(1728 + 255) / 256, 256>>>(w1, (float*)qw1, 1728);
    pack_convw_k<<<(64 * 16 * 9 + 255) / 256, 256>>>(w2, (int*)w2p, 64, 64);
    pack_convw_k<<<(128 * 16 * 9 + 255) / 256, 256>>>(w3, (int*)w3p, 128, 64);
    pack_convw_k<<<(128 * 32 * 9 + 255) / 256, 256>>>(w4, (int*)w4p, 128, 128);
    pack_convw_k<<<(256 * 32 * 9 + 255) / 256, 256>>>(w5, (int*)w5p, 256, 128);
    pack_convw_k<<<(256 * 64 * 9 + 255) / 256, 256>>>(w6, (int*)w6p, 256, 256);
    pack_fc1_k<<<(512 * 1024 + 255) / 256, 256>>>(wf1, (int*)wf1p);
    pack_fc2_k<<<(10 * 512 + 255) / 256, 256>>>(wf2, (signed char*)wf2p);

    // -------- layer 1 (fp32) --------
    conv1_kernel<<<dim3(4, 512), 1024>>>(x, (const float*)qw1, g1, b1, (unsigned*)bufA);

    // -------- layer 2: 64->64 @32 --------
    conv_q<32, 32, 16, 64, 16, 8, 1><<<dim3(4, 512), 1024>>>(
        (const int*)bufA, (const int*)w2p, g2, b2, (unsigned*)bufB);

    // pool 32->16
    {
        int total = 512 * 16 * 16 * 16;
        pool_k<<<(total + 255) / 256, 256>>>((const unsigned*)bufB, (unsigned*)bufA, 16, 16, total);
    }

    // -------- layer 3: 64->128 @16 --------
    conv_q<16, 16, 16, 128, 16, 16, 1><<<dim3(8, 512), 256>>>(
        (const int*)bufA, (const int*)w3p, g3, b3, (unsigned*)bufB);

    // -------- layer 4: 128->128 @16 --------
    conv_q<16, 16, 32, 128, 16, 16, 1><<<dim3(8, 512), 256>>>(
        (const int*)bufB, (const int*)w4p, g4, b4, (unsigned*)bufA);

    // pool 16->8
    {
        int total = 512 * 32 * 8 * 8;
        pool_k<<<(total + 255) / 256, 256>>>((const unsigned*)bufA, (unsigned*)bufB, 32, 8, total);
    }

    // -------- layer 5: 128->256 @8 --------
    conv_q<8, 8, 32, 256, 16, 16, 4><<<dim3(16, 128), 256>>>(
        (const int*)bufB, (const int*)w5p, g5, b5, (unsigned*)bufA);

    // -------- layer 6: 256->256 @8 --------
    conv_q<8, 8, 64, 256, 16, 16, 4><<<dim3(16, 128), 256>>>(
        (const int*)bufA, (const int*)w6p, g6, b6, (unsigned*)bufB);

    // pool 8->4 (features: [512][64 c4][4][4] = [512][1024] words)
    {
        int total = 512 * 64 * 4 * 4;
        pool_k<<<(total + 255) / 256, 256>>>((const unsigned*)bufB, (unsigned*)bufA, 64, 4, total);
    }

    // -------- FC head --------
    fc1_kernel<<<dim3(32, 32), dim3(16, 16)>>>(
        (const int*)bufA, (const int*)wf1p, gf1, bf1, (unsigned char*)fc1o);
    fc2_kernel<<<512, 32>>>(
        (const unsigned char*)fc1o, (const signed char*)wf2p, gf2, bf2, (float*)d_out);
}

// round 3
// speedup vs baseline: 1.7744x; 1.7744x over previous
#include <cuda_runtime.h>
#include <cstdint>

// ============================================================================
// IntegerCifar10Net — 4-bit quantized CNN, B=512.
// R3: int8 tensor cores (fixed mma type string: s32.s8.s8.s32).
// Activations NHWC int8 "levels" (0..7), weights int8 levels (-7..7).
// Convs = implicit GEMM with mma.sync.m16n8k32 (exact integer accumulation),
// epilogue p=(acc/49)*g+b ; clip ; rint(p*7) ; relu -> int8 level.
// ============================================================================

__device__ __forceinline__ int qlev(float w) {
    w = fminf(fmaxf(w, -1.0f), 1.0f);
    return (int)rintf(w * 7.0f);
}

// ---------------------------------------------------------------------------
// Static scratch
// ---------------------------------------------------------------------------
__device__ signed char   g_bufA[512 * 32 * 32 * 64];   // 33.5 MB NHWC
__device__ signed char   g_bufB[512 * 32 * 32 * 64];   // 33.5 MB NHWC
__device__ float         g_qw1[64 * 3 * 9];
__device__ signed char   g_w2[64 * 9 * 64];
__device__ signed char   g_w3[128 * 9 * 64];
__device__ signed char   g_w4[128 * 9 * 128];
__device__ signed char   g_w5[256 * 9 * 128];
__device__ signed char   g_w6[256 * 9 * 256];
__device__ int           g_wf1[512 * 1024];
__device__ signed char   g_wf2[10 * 512];
__device__ unsigned char g_fc1[512 * 512];

// ---------------------------------------------------------------------------
// Weight prep
// ---------------------------------------------------------------------------
__global__ void quant_w1_k(const float* __restrict__ w, float* __restrict__ qw, int n) {
    int i = blockIdx.x * blockDim.x + threadIdx.x;
    if (i < n) qw[i] = (float)qlev(w[i]) / 7.0f;
}

// OIHW float -> [o][kpos][ci] int8
__global__ void pack_convw8(const float* __restrict__ w, signed char* __restrict__ out,
                            int COUT, int CIN) {
    int idx = blockIdx.x * blockDim.x + threadIdx.x;
    int total = COUT * 9 * CIN;
    if (idx >= total) return;
    int ci = idx % CIN;
    int t  = idx / CIN;
    int kpos = t % 9;
    int o  = t / 9;
    out[idx] = (signed char)qlev(w[(o * CIN + ci) * 9 + kpos]);
}

// wf1 [512][4096], k = c*16 + (y*4+x). Our feature byte layout: m = px*256 + c.
// word wi = px*64 + c4, byte l -> channel 4c4+l  ->  k = (4c4+l)*16 + px.
__global__ void pack_fc1_k(const float* __restrict__ w, int* __restrict__ out) {
    int idx = blockIdx.x * blockDim.x + threadIdx.x;
    if (idx >= 512 * 1024) return;
    int wi = idx % 1024;
    int o  = idx / 1024;
    int px = wi / 64;
    int c4 = wi % 64;
    unsigned word = 0;
#pragma unroll
    for (int l = 0; l < 4; l++) {
        int k = (4 * c4 + l) * 16 + px;
        int j = qlev(w[o * 4096 + k]);
        word |= (unsigned)(j & 0xFF) << (8 * l);
    }
    out[idx] = (int)word;
}

__global__ void pack_fc2_k(const float* __restrict__ w, signed char* __restrict__ out) {
    int idx = blockIdx.x * blockDim.x + threadIdx.x;
    if (idx < 10 * 512) out[idx] = (signed char)qlev(w[idx]);
}

// ---------------------------------------------------------------------------
// Conv1: fp32 input NCHW -> NHWC int8 levels
// ---------------------------------------------------------------------------
__global__ void __launch_bounds__(1024)
conv1_kernel(const float* __restrict__ x, const float* __restrict__ qw,
             const float* __restrict__ g, const float* __restrict__ b,
             signed char* __restrict__ out) {
    __shared__ float s_in[3][34][34];
    __shared__ float s_w[16][27];
    const int tid = threadIdx.x;
    const int oy = tid / 32, ox = tid % 32;
    const int n = blockIdx.y;
    const int oc0 = blockIdx.x * 16;

    for (int i = tid; i < 3 * 34 * 34; i += 1024) {
        int t = i;
        int xx = t % 34; t /= 34;
        int yy = t % 34; t /= 34;
        int c = t;
        int yi = yy - 1, xi = xx - 1;
        float v = 0.0f;
        if ((unsigned)yi < 32u && (unsigned)xi < 32u)
            v = x[((n * 3 + c) * 32 + yi) * 32 + xi];
        s_in[c][yy][xx] = v;
    }
    for (int i = tid; i < 16 * 27; i += 1024)
        s_w[i / 27][i % 27] = qw[(oc0 + i / 27) * 27 + i % 27];
    __syncthreads();

    float acc[16];
#pragma unroll
    for (int o = 0; o < 16; o++) acc[o] = 0.0f;

#pragma unroll
    for (int c = 0; c < 3; c++) {
        float wv[9];
#pragma unroll
        for (int ky = 0; ky < 3; ky++)
#pragma unroll
            for (int kx = 0; kx < 3; kx++)
                wv[ky * 3 + kx] = s_in[c][oy + ky][ox + kx];
#pragma unroll
        for (int o = 0; o < 16; o++) {
            float a = acc[o];
#pragma unroll
            for (int k = 0; k < 9; k++)
                a = fmaf(wv[k], s_w[o][c * 9 + k], a);
            acc[o] = a;
        }
    }

    // NHWC store: out[((n*32+oy)*32+ox)*64 + oc]
    size_t ob = ((size_t)(n * 1024) + oy * 32 + ox) * 64 + oc0;
#pragma unroll
    for (int j = 0; j < 4; j++) {
        unsigned word = 0;
#pragma unroll
        for (int l = 0; l < 4; l++) {
            int o = j * 4 + l;
            float p = acc[o] * g[oc0 + o] + b[oc0 + o];
            p = fminf(fmaxf(p, -1.0f), 1.0f);
            int lev = (int)rintf(p * 7.0f);
            lev = max(lev, 0);
            word |= (unsigned)lev << (8 * l);
        }
        *(unsigned*)(out + ob + 4 * j) = word;
    }
}

// ---------------------------------------------------------------------------
// int8 tensor-core conv (implicit GEMM)
//   act:    [n][H][W][CIN] int8
//   weight: [oc][9][CIN]   int8
// Block: 256 thr (8 warps). Warp tile: M=32 px, N=64 oc. Block M=256 px,
// N=64 oc (grid.x = COUT/64). CIN chunked by 64.
// ---------------------------------------------------------------------------
__device__ __forceinline__ void mma_s8(int* d, const unsigned* a, unsigned b0, unsigned b1) {
    asm volatile(
        "mma.sync.aligned.m16n8k32.row.col.s32.s8.s8.s32 "
        "{%0,%1,%2,%3},{%4,%5,%6,%7},{%8,%9},{%0,%1,%2,%3};"
        : "+r"(d[0]), "+r"(d[1]), "+r"(d[2]), "+r"(d[3])
        : "r"(a[0]), "r"(a[1]), "r"(a[2]), "r"(a[3]), "r"(b0), "r"(b1));
}

template <int H, int W, int TY, int TX, int NB, int CIN, int COUT>
__global__ void __launch_bounds__(256, 2)
conv_mma(const signed char* __restrict__ in, const signed char* __restrict__ wq,
         const float* __restrict__ g, const float* __restrict__ bb,
         signed char* __restrict__ out) {
    constexpr int KC  = 64;
    constexpr int KCP = KC + 16;            // 80-byte pitch: conflict-free
    constexpr int PXT = TY * TX;
    constexpr int SIN_PIX = NB * (TY + 2) * (TX + 2);

    extern __shared__ signed char smem[];
    signed char* s_in = smem;                       // SIN_PIX * KCP
    signed char* s_w  = smem + SIN_PIX * KCP;       // 9 * 64 * KCP

    const int tid  = threadIdx.x;
    const int warp = tid >> 5, lane = tid & 31;
    const int oc0  = blockIdx.x * 64;
    const int ty0  = (blockIdx.y / (W / TX)) * TY;
    const int tx0  = (blockIdx.y % (W / TX)) * TX;
    const int n0   = blockIdx.z * NB;

    int acc[2][8][4];
#pragma unroll
    for (int mi = 0; mi < 2; mi++)
#pragma unroll
        for (int ni = 0; ni < 8; ni++)
#pragma unroll
            for (int j = 0; j < 4; j++) acc[mi][ni][j] = 0;

    // per-lane A row base offsets (4 row groups: +0,+8,+16,+24)
    int base[4];
#pragma unroll
    for (int q = 0; q < 4; q++) {
        int row = warp * 32 + q * 8 + (lane >> 2);
        int nn = row / PXT, rem = row % PXT;
        int py = rem / TX, px = rem % TX;
        base[q] = ((nn * (TY + 2) + py) * (TX + 2) + px) * KCP + (lane & 3) * 4;
    }

    for (int c0 = 0; c0 < CIN; c0 += KC) {
        if (c0) __syncthreads();
        // ---- load input tile (with halo, zero-padded at image border) ----
        constexpr int INW = SIN_PIX * (KC / 4);
        for (int i = tid; i < INW; i += 256) {
            int cw  = i % (KC / 4);
            int pix = i / (KC / 4);
            int xx  = pix % (TX + 2);
            int yy  = (pix / (TX + 2)) % (TY + 2);
            int nn  = pix / ((TX + 2) * (TY + 2));
            int gy = ty0 + yy - 1, gx = tx0 + xx - 1;
            unsigned v = 0;
            if ((unsigned)gy < (unsigned)H && (unsigned)gx < (unsigned)W)
                v = *(const unsigned*)(in + (((size_t)(n0 + nn) * H + gy) * W + gx) * CIN + c0 + cw * 4);
            *(unsigned*)(s_in + pix * KCP + cw * 4) = v;
        }
        // ---- load weights [kpos][oc][cin-chunk] ----
        constexpr int WW = 9 * 64 * (KC / 4);
        for (int i = tid; i < WW; i += 256) {
            int cw = i % (KC / 4);
            int t  = i / (KC / 4);
            int kpos = t % 9;
            int oc   = t / 9;
            unsigned v = *(const unsigned*)(wq + ((size_t)(oc0 + oc) * 9 + kpos) * CIN + c0 + cw * 4);
            *(unsigned*)(s_w + (kpos * 64 + oc) * KCP + cw * 4) = v;
        }
        __syncthreads();

        // ---- main loop: 9 taps x (KC/32) k-steps ----
#pragma unroll
        for (int kpos = 0; kpos < 9; kpos++) {
            const int off0 = ((kpos / 3) * (TX + 2) + (kpos % 3)) * KCP;
#pragma unroll
            for (int ks = 0; ks < KC; ks += 32) {
                const int off = off0 + ks;
                unsigned a[2][4];
#pragma unroll
                for (int mi = 0; mi < 2; mi++) {
                    a[mi][0] = *(const unsigned*)(s_in + base[2 * mi]     + off);
                    a[mi][1] = *(const unsigned*)(s_in + base[2 * mi + 1] + off);
                    a[mi][2] = *(const unsigned*)(s_in + base[2 * mi]     + off + 16);
                    a[mi][3] = *(const unsigned*)(s_in + base[2 * mi + 1] + off + 16);
                }
                const signed char* wb = s_w + kpos * 64 * KCP + (lane >> 2) * KCP + ks + (lane & 3) * 4;
#pragma unroll
                for (int ni = 0; ni < 8; ni++) {
                    unsigned b0 = *(const unsigned*)(wb + ni * 8 * KCP);
                    unsigned b1 = *(const unsigned*)(wb + ni * 8 * KCP + 16);
                    mma_s8(acc[0][ni], a[0], b0, b1);
                    mma_s8(acc[1][ni], a[1], b0, b1);
                }
            }
        }
    }

    // ---- epilogue: quantized activation, NHWC int8 store ----
#pragma unroll
    for (int mi = 0; mi < 2; mi++) {
#pragma unroll
        for (int half = 0; half < 2; half++) {
            int row = warp * 32 + mi * 16 + (lane >> 2) + half * 8;
            int nn = row / PXT, rem = row % PXT;
            int py = rem / TX, px = rem % TX;
            size_t ob = (((size_t)(n0 + nn) * H + ty0 + py) * W + tx0 + px) * COUT + oc0;
#pragma unroll
            for (int ni = 0; ni < 8; ni++) {
                int col = ni * 8 + (lane & 3) * 2;
                int v0 = acc[mi][ni][half * 2 + 0];
                int v1 = acc[mi][ni][half * 2 + 1];
                float y0 = (float)v0 / 49.0f;
                float p0 = y0 * g[oc0 + col] + bb[oc0 + col];
                p0 = fminf(fmaxf(p0, -1.0f), 1.0f);
                int l0 = max((int)rintf(p0 * 7.0f), 0);
                float y1 = (float)v1 / 49.0f;
                float p1 = y1 * g[oc0 + col + 1] + bb[oc0 + col + 1];
                p1 = fminf(fmaxf(p1, -1.0f), 1.0f);
                int l1 = max((int)rintf(p1 * 7.0f), 0);
                *(unsigned short*)(out + ob + col) = (unsigned short)(l0 | (l1 << 8));
            }
        }
    }
}

// ---------------------------------------------------------------------------
// 2x2 maxpool on NHWC bytes (vectorized by 4 channels)
// ---------------------------------------------------------------------------
__global__ void pool_k(const unsigned* __restrict__ in, unsigned* __restrict__ out,
                       int Wo, int C4, int total) {
    int idx = blockIdx.x * blockDim.x + threadIdx.x;
    if (idx >= total) return;
    int c4 = idx % C4;
    int t  = idx / C4;
    int xo = t % Wo; t /= Wo;
    int yo = t % Wo;
    int n  = t / Wo;
    int Wi = 2 * Wo;
    const unsigned* p = in + (((size_t)(n * Wi) + 2 * yo) * Wi + 2 * xo) * C4 + c4;
    unsigned m0 = __vmaxu4(p[0], p[C4]);
    unsigned m1 = __vmaxu4(p[(size_t)Wi * C4], p[(size_t)Wi * C4 + C4]);
    out[idx] = __vmaxu4(m0, m1);
}

// ---------------------------------------------------------------------------
// FC1 / FC2
// ---------------------------------------------------------------------------
__global__ void fc1_kernel(const int* __restrict__ h, const int* __restrict__ w,
                           const float* __restrict__ g, const float* __restrict__ b,
                           unsigned char* __restrict__ out) {
    __shared__ int sa[16][17];
    __shared__ int sw[16][17];
    const int tx = threadIdx.x, ty = threadIdx.y;
    const int n = blockIdx.y * 16 + ty;
    const int o = blockIdx.x * 16 + tx;
    int acc = 0;
    for (int m0 = 0; m0 < 1024; m0 += 16) {
        sa[ty][tx] = h[(blockIdx.y * 16 + ty) * 1024 + m0 + tx];
        sw[ty][tx] = w[(blockIdx.x * 16 + ty) * 1024 + m0 + tx];
        __syncthreads();
#pragma unroll
        for (int mm = 0; mm < 16; mm++)
            acc = __dp4a(sa[ty][mm], sw[tx][mm], acc);
        __syncthreads();
    }
    float y = (float)acc / 49.0f;
    float p = y * g[o] + b[o];
    p = fminf(fmaxf(p, -1.0f), 1.0f);
    int lev = (int)rintf(p * 7.0f);
    lev = max(lev, 0);
    out[n * 512 + o] = (unsigned char)lev;
}

__global__ void fc2_kernel(const unsigned char* __restrict__ h,
                           const signed char* __restrict__ w,
                           const float* __restrict__ g, const float* __restrict__ b,
                           float* __restrict__ out) {
    const int n = blockIdx.x;
    const int lane = threadIdx.x;
    for (int o = 0; o < 10; o++) {
        int acc = 0;
        for (int k = lane; k < 512; k += 32)
            acc += (int)h[n * 512 + k] * (int)w[o * 512 + k];
#pragma unroll
        for (int off = 16; off > 0; off >>= 1)
            acc += __shfl_xor_sync(0xFFFFFFFFu, acc, off);
        if (lane == 0) {
            float y = (float)acc / 49.0f;
            float p = y * g[o] + b[o];
            p = fminf(fmaxf(p, -1.0f), 1.0f);
            int lev = (int)rintf(p * 7.0f);
            out[n * 10 + o] = (float)lev / 7.0f;
        }
    }
}

// ---------------------------------------------------------------------------
// Launch
// ---------------------------------------------------------------------------
extern "C" void kernel_launch(void* const* d_in, const int* in_sizes, int n_in,
                              void* d_out, int out_size) {
    const float* x   = (const float*)d_in[0];
    const float* w1  = (const float*)d_in[1];
    const float* g1  = (const float*)d_in[2];
    const float* b1  = (const float*)d_in[3];
    const float* w2  = (const float*)d_in[4];
    const float* g2  = (const float*)d_in[5];
    const float* b2  = (const float*)d_in[6];
    const float* w3  = (const float*)d_in[7];
    const float* g3  = (const float*)d_in[8];
    const float* b3  = (const float*)d_in[9];
    const float* w4  = (const float*)d_in[10];
    const float* g4  = (const float*)d_in[11];
    const float* b4  = (const float*)d_in[12];
    const float* w5  = (const float*)d_in[13];
    const float* g5  = (const float*)d_in[14];
    const float* b5  = (const float*)d_in[15];
    const float* w6  = (const float*)d_in[16];
    const float* g6  = (const float*)d_in[17];
    const float* b6  = (const float*)d_in[18];
    const float* wf1 = (const float*)d_in[19];
    const float* gf1 = (const float*)d_in[20];
    const float* bf1 = (const float*)d_in[21];
    const float* wf2 = (const float*)d_in[22];
    const float* gf2 = (const float*)d_in[23];
    const float* bf2 = (const float*)d_in[24];

    void *bufA, *bufB, *qw1, *w2p, *w3p, *w4p, *w5p, *w6p, *wf1p, *wf2p, *fc1o;
    cudaGetSymbolAddress(&bufA, g_bufA);
    cudaGetSymbolAddress(&bufB, g_bufB);
    cudaGetSymbolAddress(&qw1, g_qw1);
    cudaGetSymbolAddress(&w2p, g_w2);
    cudaGetSymbolAddress(&w3p, g_w3);
    cudaGetSymbolAddress(&w4p, g_w4);
    cudaGetSymbolAddress(&w5p, g_w5);
    cudaGetSymbolAddress(&w6p, g_w6);
    cudaGetSymbolAddress(&wf1p, g_wf1);
    cudaGetSymbolAddress(&wf2p, g_wf2);
    cudaGetSymbolAddress(&fc1o, g_fc1);

    // max dynamic smem for conv kernels
    auto k2 = conv_mma<32, 32, 16, 16, 1, 64, 64>;
    auto k3 = conv_mma<16, 16, 16, 16, 1, 64, 128>;
    auto k4 = conv_mma<16, 16, 16, 16, 1, 128, 128>;
    auto k5 = conv_mma<8, 8, 8, 8, 4, 128, 256>;
    auto k6 = conv_mma<8, 8, 8, 8, 4, 256, 256>;
    const int smemA = (1 * 18 * 18) * 80 + 9 * 64 * 80;   // 72000
    const int smemB = (4 * 10 * 10) * 80 + 9 * 64 * 80;   // 78080
    cudaFuncSetAttribute(k2, cudaFuncAttributeMaxDynamicSharedMemorySize, smemA);
    cudaFuncSetAttribute(k3, cudaFuncAttributeMaxDynamicSharedMemorySize, smemA);
    cudaFuncSetAttribute(k4, cudaFuncAttributeMaxDynamicSharedMemorySize, smemA);
    cudaFuncSetAttribute(k5, cudaFuncAttributeMaxDynamicSharedMemorySize, smemB);
    cudaFuncSetAttribute(k6, cudaFuncAttributeMaxDynamicSharedMemorySize, smemB);

    // -------- weight prep --------
    quant_w1_k<<<(1728 + 255) / 256, 256>>>(w1, (float*)qw1, 1728);
    pack_convw8<<<(64 * 9 * 64 + 255) / 256, 256>>>(w2, (signed char*)w2p, 64, 64);
    pack_convw8<<<(128 * 9 * 64 + 255) / 256, 256>>>(w3, (signed char*)w3p, 128, 64);
    pack_convw8<<<(128 * 9 * 128 + 255) / 256, 256>>>(w4, (signed char*)w4p, 128, 128);
    pack_convw8<<<(256 * 9 * 128 + 255) / 256, 256>>>(w5, (signed char*)w5p, 256, 128);
    pack_convw8<<<(256 * 9 * 256 + 255) / 256, 256>>>(w6, (signed char*)w6p, 256, 256);
    pack_fc1_k<<<(512 * 1024 + 255) / 256, 256>>>(wf1, (int*)wf1p);
    pack_fc2_k<<<(10 * 512 + 255) / 256, 256>>>(wf2, (signed char*)wf2p);

    // -------- layer 1 (fp32) -> NHWC levels in A --------
    conv1_kernel<<<dim3(4, 512), 1024>>>(x, (const float*)qw1, g1, b1, (signed char*)bufA);

    // -------- layer 2: 64->64 @32 : A -> B --------
    k2<<<dim3(1, 4, 512), 256, smemA>>>((const signed char*)bufA, (const signed char*)w2p,
                                        g2, b2, (signed char*)bufB);
    // pool 32->16 : B -> A
    {
        int total = 512 * 16 * 16 * 16;
        pool_k<<<(total + 255) / 256, 256>>>((const unsigned*)bufB, (unsigned*)bufA, 16, 16, total);
    }
    // -------- layer 3: 64->128 @16 : A -> B --------
    k3<<<dim3(2, 1, 512), 256, smemA>>>((const signed char*)bufA, (const signed char*)w3p,
                                        g3, b3, (signed char*)bufB);
    // -------- layer 4: 128->128 @16 : B -> A --------
    k4<<<dim3(2, 1, 512), 256, smemA>>>((const signed char*)bufB, (const signed char*)w4p,
                                        g4, b4, (signed char*)bufA);
    // pool 16->8 : A -> B
    {
        int total = 512 * 8 * 8 * 32;
        pool_k<<<(total + 255) / 256, 256>>>((const unsigned*)bufA, (unsigned*)bufB, 8, 32, total);
    }
    // -------- layer 5: 128->256 @8 : B -> A --------
    k5<<<dim3(4, 1, 128), 256, smemB>>>((const signed char*)bufB, (const signed char*)w5p,
                                        g5, b5, (signed char*)bufA);
    // -------- layer 6: 256->256 @8 : A -> B --------
    k6<<<dim3(4, 1, 128), 256, smemB>>>((const signed char*)bufA, (const signed char*)w6p,
                                        g6, b6, (signed char*)bufB);
    // pool 8->4 : B -> A   (features [512][1024 words])
    {
        int total = 512 * 4 * 4 * 64;
        pool_k<<<(total + 255) / 256, 256>>>((const unsigned*)bufB, (unsigned*)bufA, 4, 64, total);
    }

    // -------- FC head --------
    fc1_kernel<<<dim3(32, 32), dim3(16, 16)>>>(
        (const int*)bufA, (const int*)wf1p, gf1, bf1, (unsigned char*)fc1o);
    fc2_kernel<<<512, 32>>>(
        (const unsigned char*)fc1o, (const signed char*)wf2p, gf2, bf2, (float*)d_out);
}

// round 4
// speedup vs baseline: 1.7786x; 1.0024x over previous
#include <cuda_runtime.h>
#include <cstdint>

// ============================================================================
// IntegerCifar10Net — 4-bit quantized CNN, B=512.
// R3: int8 tensor cores (fixed mma type string: s32.s8.s8.s32).
// Activations NHWC int8 "levels" (0..7), weights int8 levels (-7..7).
// Convs = implicit GEMM with mma.sync.m16n8k32 (exact integer accumulation),
// epilogue p=(acc/49)*g+b ; clip ; rint(p*7) ; relu -> int8 level.
// ============================================================================

__device__ __forceinline__ int qlev(float w) {
    w = fminf(fmaxf(w, -1.0f), 1.0f);
    return (int)rintf(w * 7.0f);
}

// ---------------------------------------------------------------------------
// Static scratch
// ---------------------------------------------------------------------------
__device__ signed char   g_bufA[512 * 32 * 32 * 64];   // 33.5 MB NHWC
__device__ signed char   g_bufB[512 * 32 * 32 * 64];   // 33.5 MB NHWC
__device__ float         g_qw1[64 * 3 * 9];
__device__ signed char   g_w2[64 * 9 * 64];
__device__ signed char   g_w3[128 * 9 * 64];
__device__ signed char   g_w4[128 * 9 * 128];
__device__ signed char   g_w5[256 * 9 * 128];
__device__ signed char   g_w6[256 * 9 * 256];
__device__ int           g_wf1[512 * 1024];
__device__ signed char   g_wf2[10 * 512];
__device__ unsigned char g_fc1[512 * 512];

// ---------------------------------------------------------------------------
// Weight prep
// ---------------------------------------------------------------------------
__global__ void quant_w1_k(const float* __restrict__ w, float* __restrict__ qw, int n) {
    int i = blockIdx.x * blockDim.x + threadIdx.x;
    if (i < n) qw[i] = (float)qlev(w[i]) / 7.0f;
}

// OIHW float -> [o][kpos][ci] int8
__global__ void pack_convw8(const float* __restrict__ w, signed char* __restrict__ out,
                            int COUT, int CIN) {
    int idx = blockIdx.x * blockDim.x + threadIdx.x;
    int total = COUT * 9 * CIN;
    if (idx >= total) return;
    int ci = idx % CIN;
    int t  = idx / CIN;
    int kpos = t % 9;
    int o  = t / 9;
    out[idx] = (signed char)qlev(w[(o * CIN + ci) * 9 + kpos]);
}

// wf1 [512][4096], k = c*16 + (y*4+x). Our feature byte layout: m = px*256 + c.
// word wi = px*64 + c4, byte l -> channel 4c4+l  ->  k = (4c4+l)*16 + px.
__global__ void pack_fc1_k(const float* __restrict__ w, int* __restrict__ out) {
    int idx = blockIdx.x * blockDim.x + threadIdx.x;
    if (idx >= 512 * 1024) return;
    int wi = idx % 1024;
    int o  = idx / 1024;
    int px = wi / 64;
    int c4 = wi % 64;
    unsigned word = 0;
#pragma unroll
    for (int l = 0; l < 4; l++) {
        int k = (4 * c4 + l) * 16 + px;
        int j = qlev(w[o * 4096 + k]);
        word |= (unsigned)(j & 0xFF) << (8 * l);
    }
    out[idx] = (int)word;
}

__global__ void pack_fc2_k(const float* __restrict__ w, signed char* __restrict__ out) {
    int idx = blockIdx.x * blockDim.x + threadIdx.x;
    if (idx < 10 * 512) out[idx] = (signed char)qlev(w[idx]);
}

// ---------------------------------------------------------------------------
// Conv1: fp32 input NCHW -> NHWC int8 levels
// ---------------------------------------------------------------------------
__global__ void __launch_bounds__(1024)
conv1_kernel(const float* __restrict__ x, const float* __restrict__ qw,
             const float* __restrict__ g, const float* __restrict__ b,
             signed char* __restrict__ out) {
    __shared__ float s_in[3][34][34];
    __shared__ float s_w[16][27];
    const int tid = threadIdx.x;
    const int oy = tid / 32, ox = tid % 32;
    const int n = blockIdx.y;
    const int oc0 = blockIdx.x * 16;

    for (int i = tid; i < 3 * 34 * 34; i += 1024) {
        int t = i;
        int xx = t % 34; t /= 34;
        int yy = t % 34; t /= 34;
        int c = t;
        int yi = yy - 1, xi = xx - 1;
        float v = 0.0f;
        if ((unsigned)yi < 32u && (unsigned)xi < 32u)
            v = x[((n * 3 + c) * 32 + yi) * 32 + xi];
        s_in[c][yy][xx] = v;
    }
    for (int i = tid; i < 16 * 27; i += 1024)
        s_w[i / 27][i % 27] = qw[(oc0 + i / 27) * 27 + i % 27];
    __syncthreads();

    float acc[16];
#pragma unroll
    for (int o = 0; o < 16; o++) acc[o] = 0.0f;

#pragma unroll
    for (int c = 0; c < 3; c++) {
        float wv[9];
#pragma unroll
        for (int ky = 0; ky < 3; ky++)
#pragma unroll
            for (int kx = 0; kx < 3; kx++)
                wv[ky * 3 + kx] = s_in[c][oy + ky][ox + kx];
#pragma unroll
        for (int o = 0; o < 16; o++) {
            float a = acc[o];
#pragma unroll
            for (int k = 0; k < 9; k++)
                a = fmaf(wv[k], s_w[o][c * 9 + k], a);
            acc[o] = a;
        }
    }

    // NHWC store: out[((n*32+oy)*32+ox)*64 + oc]
    size_t ob = ((size_t)(n * 1024) + oy * 32 + ox) * 64 + oc0;
#pragma unroll
    for (int j = 0; j < 4; j++) {
        unsigned word = 0;
#pragma unroll
        for (int l = 0; l < 4; l++) {
            int o = j * 4 + l;
            float p = acc[o] * g[oc0 + o] + b[oc0 + o];
            p = fminf(fmaxf(p, -1.0f), 1.0f);
            int lev = (int)rintf(p * 7.0f);
            lev = max(lev, 0);
            word |= (unsigned)lev << (8 * l);
        }
        *(unsigned*)(out + ob + 4 * j) = word;
    }
}

// ---------------------------------------------------------------------------
// int8 tensor-core conv (implicit GEMM)
//   act:    [n][H][W][CIN] int8
//   weight: [oc][9][CIN]   int8
// Block: 256 thr (8 warps). Warp tile: M=32 px, N=64 oc. Block M=256 px,
// N=64 oc (grid.x = COUT/64). CIN chunked by 64.
// ---------------------------------------------------------------------------
__device__ __forceinline__ void mma_s8(int* d, const unsigned* a, unsigned b0, unsigned b1) {
    asm volatile(
        "mma.sync.aligned.m16n8k32.row.col.s32.s8.s8.s32 "
        "{%0,%1,%2,%3},{%4,%5,%6,%7},{%8,%9},{%0,%1,%2,%3};"
        : "+r"(d[0]), "+r"(d[1]), "+r"(d[2]), "+r"(d[3])
        : "r"(a[0]), "r"(a[1]), "r"(a[2]), "r"(a[3]), "r"(b0), "r"(b1));
}

template <int H, int W, int TY, int TX, int NB, int CIN, int COUT>
__global__ void __launch_bounds__(256, 2)
conv_mma(const signed char* __restrict__ in, const signed char* __restrict__ wq,
         const float* __restrict__ g, const float* __restrict__ bb,
         signed char* __restrict__ out) {
    constexpr int KC  = 64;
    constexpr int KCP = KC + 16;            // 80-byte pitch: conflict-free
    constexpr int PXT = TY * TX;
    constexpr int SIN_PIX = NB * (TY + 2) * (TX + 2);

    extern __shared__ signed char smem[];
    signed char* s_in = smem;                       // SIN_PIX * KCP
    signed char* s_w  = smem + SIN_PIX * KCP;       // 9 * 64 * KCP

    const int tid  = threadIdx.x;
    const int warp = tid >> 5, lane = tid & 31;
    const int oc0  = blockIdx.x * 64;
    const int ty0  = (blockIdx.y / (W / TX)) * TY;
    const int tx0  = (blockIdx.y % (W / TX)) * TX;
    const int n0   = blockIdx.z * NB;

    int acc[2][8][4];
#pragma unroll
    for (int mi = 0; mi < 2; mi++)
#pragma unroll
        for (int ni = 0; ni < 8; ni++)
#pragma unroll
            for (int j = 0; j < 4; j++) acc[mi][ni][j] = 0;

    // per-lane A row base offsets (4 row groups: +0,+8,+16,+24)
    int base[4];
#pragma unroll
    for (int q = 0; q < 4; q++) {
        int row = warp * 32 + q * 8 + (lane >> 2);
        int nn = row / PXT, rem = row % PXT;
        int py = rem / TX, px = rem % TX;
        base[q] = ((nn * (TY + 2) + py) * (TX + 2) + px) * KCP + (lane & 3) * 4;
    }

    for (int c0 = 0; c0 < CIN; c0 += KC) {
        if (c0) __syncthreads();
        // ---- load input tile (with halo, zero-padded at image border) ----
        constexpr int INW = SIN_PIX * (KC / 4);
        for (int i = tid; i < INW; i += 256) {
            int cw  = i % (KC / 4);
            int pix = i / (KC / 4);
            int xx  = pix % (TX + 2);
            int yy  = (pix / (TX + 2)) % (TY + 2);
            int nn  = pix / ((TX + 2) * (TY + 2));
            int gy = ty0 + yy - 1, gx = tx0 + xx - 1;
            unsigned v = 0;
            if ((unsigned)gy < (unsigned)H && (unsigned)gx < (unsigned)W)
                v = *(const unsigned*)(in + (((size_t)(n0 + nn) * H + gy) * W + gx) * CIN + c0 + cw * 4);
            *(unsigned*)(s_in + pix * KCP + cw * 4) = v;
        }
        // ---- load weights [kpos][oc][cin-chunk] ----
        constexpr int WW = 9 * 64 * (KC / 4);
        for (int i = tid; i < WW; i += 256) {
            int cw = i % (KC / 4);
            int t  = i / (KC / 4);
            int kpos = t % 9;
            int oc   = t / 9;
            unsigned v = *(const unsigned*)(wq + ((size_t)(oc0 + oc) * 9 + kpos) * CIN + c0 + cw * 4);
            *(unsigned*)(s_w + (kpos * 64 + oc) * KCP + cw * 4) = v;
        }
        __syncthreads();

        // ---- main loop: 9 taps x (KC/32) k-steps ----
#pragma unroll
        for (int kpos = 0; kpos < 9; kpos++) {
            const int off0 = ((kpos / 3) * (TX + 2) + (kpos % 3)) * KCP;
#pragma unroll
            for (int ks = 0; ks < KC; ks += 32) {
                const int off = off0 + ks;
                unsigned a[2][4];
#pragma unroll
                for (int mi = 0; mi < 2; mi++) {
                    a[mi][0] = *(const unsigned*)(s_in + base[2 * mi]     + off);
                    a[mi][1] = *(const unsigned*)(s_in + base[2 * mi + 1] + off);
                    a[mi][2] = *(const unsigned*)(s_in + base[2 * mi]     + off + 16);
                    a[mi][3] = *(const unsigned*)(s_in + base[2 * mi + 1] + off + 16);
                }
                const signed char* wb = s_w + kpos * 64 * KCP + (lane >> 2) * KCP + ks + (lane & 3) * 4;
#pragma unroll
                for (int ni = 0; ni < 8; ni++) {
                    unsigned b0 = *(const unsigned*)(wb + ni * 8 * KCP);
                    unsigned b1 = *(const unsigned*)(wb + ni * 8 * KCP + 16);
                    mma_s8(acc[0][ni], a[0], b0, b1);
                    mma_s8(acc[1][ni], a[1], b0, b1);
                }
            }
        }
    }

    // ---- epilogue: quantized activation, NHWC int8 store ----
#pragma unroll
    for (int mi = 0; mi < 2; mi++) {
#pragma unroll
        for (int half = 0; half < 2; half++) {
            int row = warp * 32 + mi * 16 + (lane >> 2) + half * 8;
            int nn = row / PXT, rem = row % PXT;
            int py = rem / TX, px = rem % TX;
            size_t ob = (((size_t)(n0 + nn) * H + ty0 + py) * W + tx0 + px) * COUT + oc0;
#pragma unroll
            for (int ni = 0; ni < 8; ni++) {
                int col = ni * 8 + (lane & 3) * 2;
                int v0 = acc[mi][ni][half * 2 + 0];
                int v1 = acc[mi][ni][half * 2 + 1];
                float y0 = (float)v0 / 49.0f;
                float p0 = y0 * g[oc0 + col] + bb[oc0 + col];
                p0 = fminf(fmaxf(p0, -1.0f), 1.0f);
                int l0 = max((int)rintf(p0 * 7.0f), 0);
                float y1 = (float)v1 / 49.0f;
                float p1 = y1 * g[oc0 + col + 1] + bb[oc0 + col + 1];
                p1 = fminf(fmaxf(p1, -1.0f), 1.0f);
                int l1 = max((int)rintf(p1 * 7.0f), 0);
                *(unsigned short*)(out + ob + col) = (unsigned short)(l0 | (l1 << 8));
            }
        }
    }
}

// ---------------------------------------------------------------------------
// 2x2 maxpool on NHWC bytes (vectorized by 4 channels)
// ---------------------------------------------------------------------------
__global__ void pool_k(const unsigned* __restrict__ in, unsigned* __restrict__ out,
                       int Wo, int C4, int total) {
    int idx = blockIdx.x * blockDim.x + threadIdx.x;
    if (idx >= total) return;
    int c4 = idx % C4;
    int t  = idx / C4;
    int xo = t % Wo; t /= Wo;
    int yo = t % Wo;
    int n  = t / Wo;
    int Wi = 2 * Wo;
    const unsigned* p = in + (((size_t)(n * Wi) + 2 * yo) * Wi + 2 * xo) * C4 + c4;
    unsigned m0 = __vmaxu4(p[0], p[C4]);
    unsigned m1 = __vmaxu4(p[(size_t)Wi * C4], p[(size_t)Wi * C4 + C4]);
    out[idx] = __vmaxu4(m0, m1);
}

// ---------------------------------------------------------------------------
// FC1 / FC2
// ---------------------------------------------------------------------------
__global__ void fc1_kernel(const int* __restrict__ h, const int* __restrict__ w,
                           const float* __restrict__ g, const float* __restrict__ b,
                           unsigned char* __restrict__ out) {
    __shared__ int sa[16][17];
    __shared__ int sw[16][17];
    const int tx = threadIdx.x, ty = threadIdx.y;
    const int n = blockIdx.y * 16 + ty;
    const int o = blockIdx.x * 16 + tx;
    int acc = 0;
    for (int m0 = 0; m0 < 1024; m0 += 16) {
        sa[ty][tx] = h[(blockIdx.y * 16 + ty) * 1024 + m0 + tx];
        sw[ty][tx] = w[(blockIdx.x * 16 + ty) * 1024 + m0 + tx];
        __syncthreads();
#pragma unroll
        for (int mm = 0; mm < 16; mm++)
            acc = __dp4a(sa[ty][mm], sw[tx][mm], acc);
        __syncthreads();
    }
    float y = (float)acc / 49.0f;
    float p = y * g[o] + b[o];
    p = fminf(fmaxf(p, -1.0f), 1.0f);
    int lev = (int)rintf(p * 7.0f);
    lev = max(lev, 0);
    out[n * 512 + o] = (unsigned char)lev;
}

__global__ void fc2_kernel(const unsigned char* __restrict__ h,
                           const signed char* __restrict__ w,
                           const float* __restrict__ g, const float* __restrict__ b,
                           float* __restrict__ out) {
    const int n = blockIdx.x;
    const int lane = threadIdx.x;
    for (int o = 0; o < 10; o++) {
        int acc = 0;
        for (int k = lane; k < 512; k += 32)
            acc += (int)h[n * 512 + k] * (int)w[o * 512 + k];
#pragma unroll
        for (int off = 16; off > 0; off >>= 1)
            acc += __shfl_xor_sync(0xFFFFFFFFu, acc, off);
        if (lane == 0) {
            float y = (float)acc / 49.0f;
            float p = y * g[o] + b[o];
            p = fminf(fmaxf(p, -1.0f), 1.0f);
            int lev = (int)rintf(p * 7.0f);
            out[n * 10 + o] = (float)lev / 7.0f;
        }
    }
}

// ---------------------------------------------------------------------------
// Launch
// ---------------------------------------------------------------------------
extern "C" void kernel_launch(void* const* d_in, const int* in_sizes, int n_in,
                              void* d_out, int out_size) {
    const float* x   = (const float*)d_in[0];
    const float* w1  = (const float*)d_in[1];
    const float* g1  = (const float*)d_in[2];
    const float* b1  = (const float*)d_in[3];
    const float* w2  = (const float*)d_in[4];
    const float* g2  = (const float*)d_in[5];
    const float* b2  = (const float*)d_in[6];
    const float* w3  = (const float*)d_in[7];
    const float* g3  = (const float*)d_in[8];
    const float* b3  = (const float*)d_in[9];
    const float* w4  = (const float*)d_in[10];
    const float* g4  = (const float*)d_in[11];
    const float* b4  = (const float*)d_in[12];
    const float* w5  = (const float*)d_in[13];
    const float* g5  = (const float*)d_in[14];
    const float* b5  = (const float*)d_in[15];
    const float* w6  = (const float*)d_in[16];
    const float* g6  = (const float*)d_in[17];
    const float* b6  = (const float*)d_in[18];
    const float* wf1 = (const float*)d_in[19];
    const float* gf1 = (const float*)d_in[20];
    const float* bf1 = (const float*)d_in[21];
    const float* wf2 = (const float*)d_in[22];
    const float* gf2 = (const float*)d_in[23];
    const float* bf2 = (const float*)d_in[24];

    void *bufA, *bufB, *qw1, *w2p, *w3p, *w4p, *w5p, *w6p, *wf1p, *wf2p, *fc1o;
    cudaGetSymbolAddress(&bufA, g_bufA);
    cudaGetSymbolAddress(&bufB, g_bufB);
    cudaGetSymbolAddress(&qw1, g_qw1);
    cudaGetSymbolAddress(&w2p, g_w2);
    cudaGetSymbolAddress(&w3p, g_w3);
    cudaGetSymbolAddress(&w4p, g_w4);
    cudaGetSymbolAddress(&w5p, g_w5);
    cudaGetSymbolAddress(&w6p, g_w6);
    cudaGetSymbolAddress(&wf1p, g_wf1);
    cudaGetSymbolAddress(&wf2p, g_wf2);
    cudaGetSymbolAddress(&fc1o, g_fc1);

    // max dynamic smem for conv kernels
    auto k2 = conv_mma<32, 32, 16, 16, 1, 64, 64>;
    auto k3 = conv_mma<16, 16, 16, 16, 1, 64, 128>;
    auto k4 = conv_mma<16, 16, 16, 16, 1, 128, 128>;
    auto k5 = conv_mma<8, 8, 8, 8, 4, 128, 256>;
    auto k6 = conv_mma<8, 8, 8, 8, 4, 256, 256>;
    const int smemA = (1 * 18 * 18) * 80 + 9 * 64 * 80;   // 72000
    const int smemB = (4 * 10 * 10) * 80 + 9 * 64 * 80;   // 78080
    cudaFuncSetAttribute(k2, cudaFuncAttributeMaxDynamicSharedMemorySize, smemA);
    cudaFuncSetAttribute(k3, cudaFuncAttributeMaxDynamicSharedMemorySize, smemA);
    cudaFuncSetAttribute(k4, cudaFuncAttributeMaxDynamicSharedMemorySize, smemA);
    cudaFuncSetAttribute(k5, cudaFuncAttributeMaxDynamicSharedMemorySize, smemB);
    cudaFuncSetAttribute(k6, cudaFuncAttributeMaxDynamicSharedMemorySize, smemB);

    // -------- weight prep --------
    quant_w1_k<<<(1728 + 255) / 256, 256>>>(w1, (float*)qw1, 1728);
    pack_convw8<<<(64 * 9 * 64 + 255) / 256, 256>>>(w2, (signed char*)w2p, 64, 64);
    pack_convw8<<<(128 * 9 * 64 + 255) / 256, 256>>>(w3, (signed char*)w3p, 128, 64);
    pack_convw8<<<(128 * 9 * 128 + 255) / 256, 256>>>(w4, (signed char*)w4p, 128, 128);
    pack_convw8<<<(256 * 9 * 128 + 255) / 256, 256>>>(w5, (signed char*)w5p, 256, 128);
    pack_convw8<<<(256 * 9 * 256 + 255) / 256, 256>>>(w6, (signed char*)w6p, 256, 256);
    pack_fc1_k<<<(512 * 1024 + 255) / 256, 256>>>(wf1, (int*)wf1p);
    pack_fc2_k<<<(10 * 512 + 255) / 256, 256>>>(wf2, (signed char*)wf2p);

    // -------- layer 1 (fp32) -> NHWC levels in A --------
    conv1_kernel<<<dim3(4, 512), 1024>>>(x, (const float*)qw1, g1, b1, (signed char*)bufA);

    // -------- layer 2: 64->64 @32 : A -> B --------
    k2<<<dim3(1, 4, 512), 256, smemA>>>((const signed char*)bufA, (const signed char*)w2p,
                                        g2, b2, (signed char*)bufB);
    // pool 32->16 : B -> A
    {
        int total = 512 * 16 * 16 * 16;
        pool_k<<<(total + 255) / 256, 256>>>((const unsigned*)bufB, (unsigned*)bufA, 16, 16, total);
    }
    // -------- layer 3: 64->128 @16 : A -> B --------
    k3<<<dim3(2, 1, 512), 256, smemA>>>((const signed char*)bufA, (const signed char*)w3p,
                                        g3, b3, (signed char*)bufB);
    // -------- layer 4: 128->128 @16 : B -> A --------
    k4<<<dim3(2, 1, 512), 256, smemA>>>((const signed char*)bufB, (const signed char*)w4p,
                                        g4, b4, (signed char*)bufA);
    // pool 16->8 : A -> B
    {
        int total = 512 * 8 * 8 * 32;
        pool_k<<<(total + 255) / 256, 256>>>((const unsigned*)bufA, (unsigned*)bufB, 8, 32, total);
    }
    // -------- layer 5: 128->256 @8 : B -> A --------
    k5<<<dim3(4, 1, 128), 256, smemB>>>((const signed char*)bufB, (const signed char*)w5p,
                                        g5, b5, (signed char*)bufA);
    // -------- layer 6: 256->256 @8 : A -> B --------
    k6<<<dim3(4, 1, 128), 256, smemB>>>((const signed char*)bufA, (const signed char*)w6p,
                                        g6, b6, (signed char*)bufB);
    // pool 8->4 : B -> A   (features [512][1024 words])
    {
        int total = 512 * 4 * 4 * 64;
        pool_k<<<(total + 255) / 256, 256>>>((const unsigned*)bufB, (unsigned*)bufA, 4, 64, total);
    }

    // -------- FC head --------
    fc1_kernel<<<dim3(32, 32), dim3(16, 16)>>>(
        (const int*)bufA, (const int*)wf1p, gf1, bf1, (unsigned char*)fc1o);
    fc2_kernel<<<512, 32>>>(
        (const unsigned char*)fc1o, (const signed char*)wf2p, gf2, bf2, (float*)d_out);
}

// round 6
// speedup vs baseline: 2.2274x; 1.2524x over previous
#include <cuda_runtime.h>
#include <cuda_bf16.h>
#include <cstdint>

// ============================================================================
// IntegerCifar10Net R6: warp-level bf16 HMMA convs (mma.sync.m16n8k16,
// non-family-specific => compiles for plain sm_103 target).
// Activations bf16 NHWC "levels" (0..7), weights bf16 levels (-7..7).
// fp32 accumulation is exact for these integers. Epilogue identical to R3.
// ============================================================================

__device__ __forceinline__ int qlev(float w) {
    w = fminf(fmaxf(w, -1.0f), 1.0f);
    return (int)rintf(w * 7.0f);
}
__device__ __forceinline__ unsigned pack_bf16x2(float lo, float hi) {
    unsigned r;
    asm("cvt.rn.bf16x2.f32 %0, %1, %2;" : "=r"(r) : "f"(hi), "f"(lo));
    return r;
}

// ---------------- scratch ----------------
__device__ __nv_bfloat16 g_bufA[512 * 32 * 32 * 64];
__device__ __nv_bfloat16 g_bufB[512 * 32 * 32 * 64];
__device__ float         g_qw1[64 * 3 * 9];
__device__ __nv_bfloat16 g_wb2[9 * 1 * 64 * 64];
__device__ __nv_bfloat16 g_wb3[9 * 1 * 128 * 64];
__device__ __nv_bfloat16 g_wb4[9 * 2 * 128 * 64];
__device__ __nv_bfloat16 g_wb5[9 * 2 * 256 * 64];
__device__ __nv_bfloat16 g_wb6[9 * 4 * 256 * 64];
__device__ int           g_wf1[512 * 1024];
__device__ signed char   g_wf2[10 * 512];
__device__ unsigned char g_fc1[512 * 512];

// ---------------- weight prep ----------------
__global__ void quant_w1_k(const float* __restrict__ w, float* __restrict__ qw, int n) {
    int i = blockIdx.x * blockDim.x + threadIdx.x;
    if (i < n) qw[i] = (float)qlev(w[i]) / 7.0f;
}
// OIHW float -> bf16 [kpos][ch][oc][64]
__global__ void pack_convw_bf16(const float* __restrict__ w, __nv_bfloat16* __restrict__ out,
                                int COUT, int CIN) {
    int idx = blockIdx.x * blockDim.x + threadIdx.x;
    int NCH = CIN / 64;
    if (idx >= COUT * 9 * CIN) return;
    int j = idx % 64;
    int t = idx / 64;
    int oc = t % COUT; t /= COUT;
    int ch = t % NCH;
    int kpos = t / NCH;
    out[idx] = __float2bfloat16((float)qlev(w[(oc * CIN + ch * 64 + j) * 9 + kpos]));
}
__global__ void pack_fc1_k(const float* __restrict__ w, int* __restrict__ out) {
    int idx = blockIdx.x * blockDim.x + threadIdx.x;
    if (idx >= 512 * 1024) return;
    int wi = idx % 1024, o = idx / 1024;
    int px = wi / 64, c4 = wi % 64;
    unsigned word = 0;
#pragma unroll
    for (int l = 0; l < 4; l++) {
        int k = (4 * c4 + l) * 16 + px;
        word |= (unsigned)(qlev(w[o * 4096 + k]) & 0xFF) << (8 * l);
    }
    out[idx] = (int)word;
}
__global__ void pack_fc2_k(const float* __restrict__ w, signed char* __restrict__ out) {
    int idx = blockIdx.x * blockDim.x + threadIdx.x;
    if (idx < 10 * 512) out[idx] = (signed char)qlev(w[idx]);
}

// ---------------- conv1: fp32 NCHW -> bf16 NHWC levels ----------------
__global__ void __launch_bounds__(1024)
conv1_kernel(const float* __restrict__ x, const float* __restrict__ qw,
             const float* __restrict__ g, const float* __restrict__ b,
             __nv_bfloat16* __restrict__ out) {
    __shared__ float s_in[3][34][34];
    __shared__ float s_w[16][27];
    const int tid = threadIdx.x;
    const int oy = tid / 32, ox = tid % 32;
    const int n = blockIdx.y;
    const int oc0 = blockIdx.x * 16;
    for (int i = tid; i < 3 * 34 * 34; i += 1024) {
        int t = i;
        int xx = t % 34; t /= 34;
        int yy = t % 34; t /= 34;
        int c = t;
        int yi = yy - 1, xi = xx - 1;
        float v = 0.0f;
        if ((unsigned)yi < 32u && (unsigned)xi < 32u)
            v = x[((n * 3 + c) * 32 + yi) * 32 + xi];
        s_in[c][yy][xx] = v;
    }
    for (int i = tid; i < 16 * 27; i += 1024)
        s_w[i / 27][i % 27] = qw[(oc0 + i / 27) * 27 + i % 27];
    __syncthreads();
    float acc[16];
#pragma unroll
    for (int o = 0; o < 16; o++) acc[o] = 0.0f;
#pragma unroll
    for (int c = 0; c < 3; c++) {
        float wv[9];
#pragma unroll
        for (int ky = 0; ky < 3; ky++)
#pragma unroll
            for (int kx = 0; kx < 3; kx++)
                wv[ky * 3 + kx] = s_in[c][oy + ky][ox + kx];
#pragma unroll
        for (int o = 0; o < 16; o++) {
            float a = acc[o];
#pragma unroll
            for (int k = 0; k < 9; k++) a = fmaf(wv[k], s_w[o][c * 9 + k], a);
            acc[o] = a;
        }
    }
    unsigned* ob = (unsigned*)(out + ((size_t)(n * 1024) + oy * 32 + ox) * 64 + oc0);
#pragma unroll
    for (int j = 0; j < 8; j++) {
        float lv[2];
#pragma unroll
        for (int l = 0; l < 2; l++) {
            int o = j * 2 + l;
            float p = acc[o] * g[oc0 + o] + b[oc0 + o];
            p = fminf(fmaxf(p, -1.0f), 1.0f);
            lv[l] = fmaxf(rintf(p * 7.0f), 0.0f);
        }
        ob[j] = pack_bf16x2(lv[0], lv[1]);
    }
}

// ---------------- bf16 HMMA conv (implicit GEMM) ----------------
__device__ __forceinline__ void mma_bf16(float* d, const unsigned* a, unsigned b0, unsigned b1) {
    asm volatile(
        "mma.sync.aligned.m16n8k16.row.col.f32.bf16.bf16.f32 "
        "{%0,%1,%2,%3},{%4,%5,%6,%7},{%8,%9},{%0,%1,%2,%3};"
        : "+f"(d[0]), "+f"(d[1]), "+f"(d[2]), "+f"(d[3])
        : "r"(a[0]), "r"(a[1]), "r"(a[2]), "r"(a[3]), "r"(b0), "r"(b1));
}

// act: [n][H][W][CIN] bf16 ; weight: [kpos][ch][oc][64] bf16
// Block 256 thr (8 warps); warp tile M=32 px, N=64 oc; block M=256 px.
// grid.x = COUT/64 ; CIN chunked by 64 channels (KCP=144B pitch, conflict-free).
template <int H, int W, int TY, int TX, int NB, int CIN, int COUT>
__global__ void __launch_bounds__(256)
conv_hmma(const __nv_bfloat16* __restrict__ in, const __nv_bfloat16* __restrict__ wq,
          const float* __restrict__ g, const float* __restrict__ bb,
          __nv_bfloat16* __restrict__ out) {
    constexpr int NCH = CIN / 64;
    constexpr int KCP = 144;                 // 128B chunk + 16B pad
    constexpr int PXT = TY * TX;
    constexpr int SIN_PIX = NB * (TY + 2) * (TX + 2);

    extern __shared__ char smem[];
    char* s_in = smem;                       // SIN_PIX * KCP
    char* s_w  = smem + SIN_PIX * KCP;       // 9 * 64 * KCP

    const int tid  = threadIdx.x;
    const int warp = tid >> 5, lane = tid & 31;
    const int oc0  = blockIdx.x * 64;
    const int ty0  = (blockIdx.y / (W / TX)) * TY;
    const int tx0  = (blockIdx.y % (W / TX)) * TX;
    const int n0   = blockIdx.z * NB;
    const char* inb = (const char*)in;
    const char* wqb = (const char*)wq;

    float acc[2][8][4];
#pragma unroll
    for (int mi = 0; mi < 2; mi++)
#pragma unroll
        for (int ni = 0; ni < 8; ni++)
#pragma unroll
            for (int j = 0; j < 4; j++) acc[mi][ni][j] = 0.0f;

    // per-lane A row base byte offsets (4 row groups: +0,+8,+16,+24)
    int base[4];
#pragma unroll
    for (int q = 0; q < 4; q++) {
        int row = warp * 32 + q * 8 + (lane >> 2);
        int nn = row / PXT, rem = row % PXT;
        int py = rem / TX, px = rem % TX;
        base[q] = ((nn * (TY + 2) + py) * (TX + 2) + px) * KCP + (lane & 3) * 4;
    }

    for (int ch = 0; ch < NCH; ch++) {
        if (ch) __syncthreads();
        // ---- stage A chunk (halo, zero-padded) : 16B per thread-iter ----
        for (int u = tid; u < SIN_PIX * 8; u += 256) {
            int j   = u & 7;
            int pix = u >> 3;
            int xx  = pix % (TX + 2);
            int yy  = (pix / (TX + 2)) % (TY + 2);
            int nn  = pix / ((TX + 2) * (TY + 2));
            int gy = ty0 + yy - 1, gx = tx0 + xx - 1;
            uint4 v = make_uint4(0, 0, 0, 0);
            if ((unsigned)gy < (unsigned)H && (unsigned)gx < (unsigned)W)
                v = *(const uint4*)(inb +
                    ((((size_t)(n0 + nn) * H + gy) * W + gx) * CIN + ch * 64 + j * 8) * 2);
            *(uint4*)(s_in + pix * KCP + j * 16) = v;
        }
        // ---- stage weights: all 9 taps of this chunk, 64 local oc ----
        for (int u = tid; u < 9 * 64 * 8; u += 256) {
            int kpos = u >> 9;
            int rem  = u & 511;
            int r = rem >> 3, j = rem & 7;
            uint4 v = *(const uint4*)(wqb +
                (((size_t)(kpos * NCH + ch) * COUT + oc0 + r) * 64 + j * 8) * 2);
            *(uint4*)(s_w + (kpos * 64 + r) * KCP + j * 16) = v;
        }
        __syncthreads();

        // ---- compute: 9 taps x 4 k-steps (16 ch each) ----
#pragma unroll
        for (int kpos = 0; kpos < 9; kpos++) {
            const int off0 = ((kpos / 3) * (TX + 2) + (kpos % 3)) * KCP;
#pragma unroll
            for (int ks = 0; ks < 4; ks++) {
                const int off = off0 + ks * 32;
                unsigned a[2][4];
#pragma unroll
                for (int mi = 0; mi < 2; mi++) {
                    a[mi][0] = *(const unsigned*)(s_in + base[2 * mi]     + off);
                    a[mi][1] = *(const unsigned*)(s_in + base[2 * mi + 1] + off);
                    a[mi][2] = *(const unsigned*)(s_in + base[2 * mi]     + off + 16);
                    a[mi][3] = *(const unsigned*)(s_in + base[2 * mi + 1] + off + 16);
                }
                const char* wb = s_w + (kpos * 64 + (lane >> 2)) * KCP + ks * 32 + (lane & 3) * 4;
#pragma unroll
                for (int ni = 0; ni < 8; ni++) {
                    unsigned b0 = *(const unsigned*)(wb + ni * 8 * KCP);
                    unsigned b1 = *(const unsigned*)(wb + ni * 8 * KCP + 16);
                    mma_bf16(acc[0][ni], a[0], b0, b1);
                    mma_bf16(acc[1][ni], a[1], b0, b1);
                }
            }
        }
    }

    // ---- epilogue: quantized activation -> bf16 NHWC ----
#pragma unroll
    for (int mi = 0; mi < 2; mi++) {
#pragma unroll
        for (int half = 0; half < 2; half++) {
            int row = warp * 32 + mi * 16 + (lane >> 2) + half * 8;
            int nn = row / PXT, rem = row % PXT;
            int py = rem / TX, px = rem % TX;
            size_t ob = (((size_t)(n0 + nn) * H + ty0 + py) * W + tx0 + px) * COUT + oc0;
#pragma unroll
            for (int ni = 0; ni < 8; ni++) {
                int col = ni * 8 + (lane & 3) * 2;
                float lv[2];
#pragma unroll
                for (int l = 0; l < 2; l++) {
                    float y = acc[mi][ni][half * 2 + l] / 49.0f;
                    float p = y * g[oc0 + col + l] + bb[oc0 + col + l];
                    p = fminf(fmaxf(p, -1.0f), 1.0f);
                    lv[l] = fmaxf(rintf(p * 7.0f), 0.0f);
                }
                *(unsigned*)((char*)out + (ob + col) * 2) = pack_bf16x2(lv[0], lv[1]);
            }
        }
    }
}

// ---------------- pools ----------------
__global__ void pool_bf16(const unsigned* __restrict__ in, unsigned* __restrict__ out,
                          int Wo, int C2, int total) {
    int idx = blockIdx.x * blockDim.x + threadIdx.x;
    if (idx >= total) return;
    int c2 = idx % C2;
    int t = idx / C2;
    int xo = t % Wo; t /= Wo;
    int yo = t % Wo;
    int n = t / Wo;
    int Wi = 2 * Wo;
    const unsigned* p = in + (((size_t)n * Wi + 2 * yo) * Wi + 2 * xo) * C2 + c2;
    __nv_bfloat162 a = *(const __nv_bfloat162*)&p[0];
    __nv_bfloat162 b = *(const __nv_bfloat162*)&p[C2];
    __nv_bfloat162 c = *(const __nv_bfloat162*)&p[(size_t)Wi * C2];
    __nv_bfloat162 d = *(const __nv_bfloat162*)&p[(size_t)Wi * C2 + C2];
    __nv_bfloat162 m = __hmax2(__hmax2(a, b), __hmax2(c, d));
    out[idx] = *(unsigned*)&m;
}
// pool 8->4 on bf16 levels -> packed int8 words for FC1
__global__ void pool3_int8(const unsigned* __restrict__ in, unsigned* __restrict__ out,
                           int total) {
    int idx = blockIdx.x * blockDim.x + threadIdx.x;
    if (idx >= total) return;
    int c4 = idx % 64;
    int px = (idx / 64) % 16;
    int n = idx / 1024;
    int xo = px % 4, yo = px / 4;
    unsigned word = 0;
#pragma unroll
    for (int h = 0; h < 2; h++) {
        int c2 = c4 * 2 + h;
        const unsigned* p = in + (((size_t)n * 8 + 2 * yo) * 8 + 2 * xo) * 128 + c2;
        __nv_bfloat162 a = *(const __nv_bfloat162*)&p[0];
        __nv_bfloat162 b = *(const __nv_bfloat162*)&p[128];
        __nv_bfloat162 c = *(const __nv_bfloat162*)&p[8 * 128];
        __nv_bfloat162 d = *(const __nv_bfloat162*)&p[8 * 128 + 128];
        __nv_bfloat162 m = __hmax2(__hmax2(a, b), __hmax2(c, d));
        int v0 = (int)__low2float(m);
        int v1 = (int)__high2float(m);
        word |= ((unsigned)v0 << (16 * h)) | ((unsigned)v1 << (16 * h + 8));
    }
    out[idx] = word;
}

// ---------------- FC ----------------
__global__ void fc1_kernel(const int* __restrict__ h, const int* __restrict__ w,
                           const float* __restrict__ g, const float* __restrict__ b,
                           unsigned char* __restrict__ out) {
    __shared__ int sa[16][17];
    __shared__ int sw[16][17];
    const int tx = threadIdx.x, ty = threadIdx.y;
    const int n = blockIdx.y * 16 + ty;
    const int o = blockIdx.x * 16 + tx;
    int acc = 0;
    for (int m0 = 0; m0 < 1024; m0 += 16) {
        sa[ty][tx] = h[(blockIdx.y * 16 + ty) * 1024 + m0 + tx];
        sw[ty][tx] = w[(blockIdx.x * 16 + ty) * 1024 + m0 + tx];
        __syncthreads();
#pragma unroll
        for (int mm = 0; mm < 16; mm++) acc = __dp4a(sa[ty][mm], sw[tx][mm], acc);
        __syncthreads();
    }
    float y = (float)acc / 49.0f;
    float p = y * g[o] + b[o];
    p = fminf(fmaxf(p, -1.0f), 1.0f);
    int lev = max((int)rintf(p * 7.0f), 0);
    out[n * 512 + o] = (unsigned char)lev;
}
__global__ void fc2_kernel(const unsigned char* __restrict__ h,
                           const signed char* __restrict__ w,
                           const float* __restrict__ g, const float* __restrict__ b,
                           float* __restrict__ out) {
    const int n = blockIdx.x;
    const int lane = threadIdx.x;
    for (int o = 0; o < 10; o++) {
        int acc = 0;
        for (int k = lane; k < 512; k += 32)
            acc += (int)h[n * 512 + k] * (int)w[o * 512 + k];
#pragma unroll
        for (int off = 16; off > 0; off >>= 1)
            acc += __shfl_xor_sync(0xFFFFFFFFu, acc, off);
        if (lane == 0) {
            float y = (float)acc / 49.0f;
            float p = y * g[o] + b[o];
            p = fminf(fmaxf(p, -1.0f), 1.0f);
            out[n * 10 + o] = (float)((int)rintf(p * 7.0f)) / 7.0f;
        }
    }
}

// ---------------- launch ----------------
extern "C" void kernel_launch(void* const* d_in, const int* in_sizes, int n_in,
                              void* d_out, int out_size) {
    const float* x = (const float*)d_in[0];
    const float *w1 = (const float*)d_in[1], *g1 = (const float*)d_in[2], *b1 = (const float*)d_in[3];
    const float *w2 = (const float*)d_in[4], *g2 = (const float*)d_in[5], *b2 = (const float*)d_in[6];
    const float *w3 = (const float*)d_in[7], *g3 = (const float*)d_in[8], *b3 = (const float*)d_in[9];
    const float *w4 = (const float*)d_in[10], *g4 = (const float*)d_in[11], *b4 = (const float*)d_in[12];
    const float *w5 = (const float*)d_in[13], *g5 = (const float*)d_in[14], *b5 = (const float*)d_in[15];
    const float *w6 = (const float*)d_in[16], *g6 = (const float*)d_in[17], *b6 = (const float*)d_in[18];
    const float *wf1 = (const float*)d_in[19], *gf1 = (const float*)d_in[20], *bf1 = (const float*)d_in[21];
    const float *wf2 = (const float*)d_in[22], *gf2 = (const float*)d_in[23], *bf2 = (const float*)d_in[24];

    void *bufA, *bufB, *qw1, *w2p, *w3p, *w4p, *w5p, *w6p, *wf1p, *wf2p, *fc1o;
    cudaGetSymbolAddress(&bufA, g_bufA);
    cudaGetSymbolAddress(&bufB, g_bufB);
    cudaGetSymbolAddress(&qw1, g_qw1);
    cudaGetSymbolAddress(&w2p, g_wb2);
    cudaGetSymbolAddress(&w3p, g_wb3);
    cudaGetSymbolAddress(&w4p, g_wb4);
    cudaGetSymbolAddress(&w5p, g_wb5);
    cudaGetSymbolAddress(&w6p, g_wb6);
    cudaGetSymbolAddress(&wf1p, g_wf1);
    cudaGetSymbolAddress(&wf2p, g_wf2);
    cudaGetSymbolAddress(&fc1o, g_fc1);

    auto k2 = conv_hmma<32, 32, 16, 16, 1, 64, 64>;
    auto k3 = conv_hmma<16, 16, 16, 16, 1, 64, 128>;
    auto k4 = conv_hmma<16, 16, 16, 16, 1, 128, 128>;
    auto k5 = conv_hmma<8, 8, 8, 8, 4, 128, 256>;
    auto k6 = conv_hmma<8, 8, 8, 8, 4, 256, 256>;
    const int smA = (1 * 18 * 18) * 144 + 9 * 64 * 144;   // 46656 + 82944 = 129600
    const int smB = (4 * 10 * 10) * 144 + 9 * 64 * 144;   // 57600 + 82944 = 140544
    cudaFuncSetAttribute(k2, cudaFuncAttributeMaxDynamicSharedMemorySize, smA);
    cudaFuncSetAttribute(k3, cudaFuncAttributeMaxDynamicSharedMemorySize, smA);
    cudaFuncSetAttribute(k4, cudaFuncAttributeMaxDynamicSharedMemorySize, smA);
    cudaFuncSetAttribute(k5, cudaFuncAttributeMaxDynamicSharedMemorySize, smB);
    cudaFuncSetAttribute(k6, cudaFuncAttributeMaxDynamicSharedMemorySize, smB);

    quant_w1_k<<<7, 256>>>(w1, (float*)qw1, 1728);
    pack_convw_bf16<<<(64 * 9 * 64 + 255) / 256, 256>>>(w2, (__nv_bfloat16*)w2p, 64, 64);
    pack_convw_bf16<<<(128 * 9 * 64 + 255) / 256, 256>>>(w3, (__nv_bfloat16*)w3p, 128, 64);
    pack_convw_bf16<<<(128 * 9 * 128 + 255) / 256, 256>>>(w4, (__nv_bfloat16*)w4p, 128, 128);
    pack_convw_bf16<<<(256 * 9 * 128 + 255) / 256, 256>>>(w5, (__nv_bfloat16*)w5p, 256, 128);
    pack_convw_bf16<<<(256 * 9 * 256 + 255) / 256, 256>>>(w6, (__nv_bfloat16*)w6p, 256, 256);
    pack_fc1_k<<<(512 * 1024 + 255) / 256, 256>>>(wf1, (int*)wf1p);
    pack_fc2_k<<<20, 256>>>(wf2, (signed char*)wf2p);

    conv1_kernel<<<dim3(4, 512), 1024>>>(x, (const float*)qw1, g1, b1, (__nv_bfloat16*)bufA);

    // L2: 64->64 @32, A->B
    k2<<<dim3(1, 4, 512), 256, smA>>>((const __nv_bfloat16*)bufA, (const __nv_bfloat16*)w2p,
                                      g2, b2, (__nv_bfloat16*)bufB);
    {   // pool 32->16 (C2=32): B->A
        int total = 512 * 16 * 16 * 32;
        pool_bf16<<<(total + 255) / 256, 256>>>((const unsigned*)bufB, (unsigned*)bufA, 16, 32, total);
    }
    // L3: 64->128 @16, A->B
    k3<<<dim3(2, 1, 512), 256, smA>>>((const __nv_bfloat16*)bufA, (const __nv_bfloat16*)w3p,
                                      g3, b3, (__nv_bfloat16*)bufB);
    // L4: 128->128 @16, B->A
    k4<<<dim3(2, 1, 512), 256, smA>>>((const __nv_bfloat16*)bufB, (const __nv_bfloat16*)w4p,
                                      g4, b4, (__nv_bfloat16*)bufA);
    {   // pool 16->8 (C2=64): A->B
        int total = 512 * 8 * 8 * 64;
        pool_bf16<<<(total + 255) / 256, 256>>>((const unsigned*)bufA, (unsigned*)bufB, 8, 64, total);
    }
    // L5: 128->256 @8, B->A
    k5<<<dim3(4, 1, 128), 256, smB>>>((const __nv_bfloat16*)bufB, (const __nv_bfloat16*)w5p,
                                      g5, b5, (__nv_bfloat16*)bufA);
    // L6: 256->256 @8, A->B
    k6<<<dim3(4, 1, 128), 256, smB>>>((const __nv_bfloat16*)bufA, (const __nv_bfloat16*)w6p,
                                      g6, b6, (__nv_bfloat16*)bufB);
    {   // pool 8->4 -> packed int8 words: B->A
        int total = 512 * 16 * 64;
        pool3_int8<<<(total + 255) / 256, 256>>>((const unsigned*)bufB, (unsigned*)bufA, total);
    }

    fc1_kernel<<<dim3(32, 32), dim3(16, 16)>>>((const int*)bufA, (const int*)wf1p, gf1, bf1,
                                               (unsigned char*)fc1o);
    fc2_kernel<<<512, 32>>>((const unsigned char*)fc1o, (const signed char*)wf2p, gf2, bf2,
                            (float*)d_out);
}

// round 7
// speedup vs baseline: 3.1088x; 1.3957x over previous
#include <cuda_runtime.h>
#include <cuda_bf16.h>
#include <cstdint>

// ============================================================================
// IntegerCifar10Net R7: bf16 HMMA convs, occupancy-2 (split weight groups),
// cp.async staging, launch order tuned so ncu (-s 5 -c 1) captures conv L2.
// ============================================================================

__device__ __forceinline__ int qlev(float w) {
    w = fminf(fmaxf(w, -1.0f), 1.0f);
    return (int)rintf(w * 7.0f);
}
__device__ __forceinline__ unsigned pack_bf16x2(float lo, float hi) {
    unsigned r;
    asm("cvt.rn.bf16x2.f32 %0, %1, %2;" : "=r"(r) : "f"(hi), "f"(lo));
    return r;
}
__device__ __forceinline__ unsigned smem_u32(const void* p) {
    return (unsigned)__cvta_generic_to_shared(p);
}
__device__ __forceinline__ void cp16(unsigned dst, const void* src, int szvalid) {
    asm volatile("cp.async.cg.shared.global [%0], [%1], 16, %2;"
                 :: "r"(dst), "l"(src), "r"(szvalid) : "memory");
}
__device__ __forceinline__ void cp_commit_wait() {
    asm volatile("cp.async.commit_group;" ::: "memory");
    asm volatile("cp.async.wait_group 0;" ::: "memory");
}

// ---------------- scratch ----------------
__device__ __nv_bfloat16 g_bufA[512 * 32 * 32 * 64];
__device__ __nv_bfloat16 g_bufB[512 * 32 * 32 * 64];
__device__ float         g_qw1[64 * 3 * 9];
__device__ __nv_bfloat16 g_wb2[9 * 1 * 64 * 64];
__device__ __nv_bfloat16 g_wb3[9 * 1 * 128 * 64];
__device__ __nv_bfloat16 g_wb4[9 * 2 * 128 * 64];
__device__ __nv_bfloat16 g_wb5[9 * 2 * 256 * 64];
__device__ __nv_bfloat16 g_wb6[9 * 4 * 256 * 64];
__device__ int           g_wf1[512 * 1024];
__device__ signed char   g_wf2[10 * 512];
__device__ unsigned char g_fc1[512 * 512];

// ---------------- weight prep ----------------
__global__ void quant_w1_k(const float* __restrict__ w, float* __restrict__ qw, int n) {
    int i = blockIdx.x * blockDim.x + threadIdx.x;
    if (i < n) qw[i] = (float)qlev(w[i]) / 7.0f;
}
// OIHW float -> bf16 [kpos][ch][oc][64]
__global__ void pack_convw_bf16(const float* __restrict__ w, __nv_bfloat16* __restrict__ out,
                                int COUT, int CIN) {
    int idx = blockIdx.x * blockDim.x + threadIdx.x;
    int NCH = CIN / 64;
    if (idx >= COUT * 9 * CIN) return;
    int j = idx % 64;
    int t = idx / 64;
    int oc = t % COUT; t /= COUT;
    int ch = t % NCH;
    int kpos = t / NCH;
    out[idx] = __float2bfloat16((float)qlev(w[(oc * CIN + ch * 64 + j) * 9 + kpos]));
}
__global__ void pack_fc1_k(const float* __restrict__ w, int* __restrict__ out) {
    int idx = blockIdx.x * blockDim.x + threadIdx.x;
    if (idx >= 512 * 1024) return;
    int wi = idx % 1024, o = idx / 1024;
    int px = wi / 64, c4 = wi % 64;
    unsigned word = 0;
#pragma unroll
    for (int l = 0; l < 4; l++) {
        int k = (4 * c4 + l) * 16 + px;
        word |= (unsigned)(qlev(w[o * 4096 + k]) & 0xFF) << (8 * l);
    }
    out[idx] = (int)word;
}
__global__ void pack_fc2_k(const float* __restrict__ w, signed char* __restrict__ out) {
    int idx = blockIdx.x * blockDim.x + threadIdx.x;
    if (idx < 10 * 512) out[idx] = (signed char)qlev(w[idx]);
}

// ---------------- conv1: fp32 NCHW -> bf16 NHWC levels ----------------
__global__ void __launch_bounds__(1024)
conv1_kernel(const float* __restrict__ x, const float* __restrict__ qw,
             const float* __restrict__ g, const float* __restrict__ b,
             __nv_bfloat16* __restrict__ out) {
    __shared__ float s_in[3][34][34];
    __shared__ float s_w[16][27];
    const int tid = threadIdx.x;
    const int oy = tid / 32, ox = tid % 32;
    const int n = blockIdx.y;
    const int oc0 = blockIdx.x * 16;
    for (int i = tid; i < 3 * 34 * 34; i += 1024) {
        int t = i;
        int xx = t % 34; t /= 34;
        int yy = t % 34; t /= 34;
        int c = t;
        int yi = yy - 1, xi = xx - 1;
        float v = 0.0f;
        if ((unsigned)yi < 32u && (unsigned)xi < 32u)
            v = x[((n * 3 + c) * 32 + yi) * 32 + xi];
        s_in[c][yy][xx] = v;
    }
    for (int i = tid; i < 16 * 27; i += 1024)
        s_w[i / 27][i % 27] = qw[(oc0 + i / 27) * 27 + i % 27];
    __syncthreads();
    float acc[16];
#pragma unroll
    for (int o = 0; o < 16; o++) acc[o] = 0.0f;
#pragma unroll
    for (int c = 0; c < 3; c++) {
        float wv[9];
#pragma unroll
        for (int ky = 0; ky < 3; ky++)
#pragma unroll
            for (int kx = 0; kx < 3; kx++)
                wv[ky * 3 + kx] = s_in[c][oy + ky][ox + kx];
#pragma unroll
        for (int o = 0; o < 16; o++) {
            float a = acc[o];
#pragma unroll
            for (int k = 0; k < 9; k++) a = fmaf(wv[k], s_w[o][c * 9 + k], a);
            acc[o] = a;
        }
    }
    unsigned* ob = (unsigned*)(out + ((size_t)(n * 1024) + oy * 32 + ox) * 64 + oc0);
#pragma unroll
    for (int j = 0; j < 8; j++) {
        float lv[2];
#pragma unroll
        for (int l = 0; l < 2; l++) {
            int o = j * 2 + l;
            float p = acc[o] * g[oc0 + o] + b[oc0 + o];
            p = fminf(fmaxf(p, -1.0f), 1.0f);
            lv[l] = fmaxf(rintf(p * 7.0f), 0.0f);
        }
        ob[j] = pack_bf16x2(lv[0], lv[1]);
    }
}

// ---------------- bf16 HMMA conv (implicit GEMM, occupancy 2) ----------------
__device__ __forceinline__ void mma_bf16(float* d, const unsigned* a, unsigned b0, unsigned b1) {
    asm volatile(
        "mma.sync.aligned.m16n8k16.row.col.f32.bf16.bf16.f32 "
        "{%0,%1,%2,%3},{%4,%5,%6,%7},{%8,%9},{%0,%1,%2,%3};"
        : "+f"(d[0]), "+f"(d[1]), "+f"(d[2]), "+f"(d[3])
        : "r"(a[0]), "r"(a[1]), "r"(a[2]), "r"(a[3]), "r"(b0), "r"(b1));
}

// act [n][H][W][CIN] bf16 ; weight [kpos][ch][oc][64] bf16
// 8 warps; warp tile M=32 px, N=64 oc; block M=256 px; weights staged in
// 5-tap + 4-tap groups (smem cut ~40% => 2 CTAs/SM).
template <int H, int W, int TY, int TX, int NB, int CIN, int COUT>
__global__ void __launch_bounds__(256, 2)
conv_hmma(const __nv_bfloat16* __restrict__ in, const __nv_bfloat16* __restrict__ wq,
          const float* __restrict__ g, const float* __restrict__ bb,
          __nv_bfloat16* __restrict__ out) {
    constexpr int NCH = CIN / 64;
    constexpr int KCP = 144;                 // 128B chunk + 16B pad
    constexpr int PXT = TY * TX;
    constexpr int SIN_PIX = NB * (TY + 2) * (TX + 2);

    extern __shared__ char smem[];
    char* s_in = smem;                       // SIN_PIX * KCP
    char* s_w  = smem + SIN_PIX * KCP;       // 5 * 64 * KCP (max group)

    const int tid  = threadIdx.x;
    const int warp = tid >> 5, lane = tid & 31;
    const int oc0  = blockIdx.x * 64;
    const int ty0  = (blockIdx.y / (W / TX)) * TY;
    const int tx0  = (blockIdx.y % (W / TX)) * TX;
    const int n0   = blockIdx.z * NB;
    const char* inb = (const char*)in;
    const char* wqb = (const char*)wq;

    float acc[2][8][4];
#pragma unroll
    for (int mi = 0; mi < 2; mi++)
#pragma unroll
        for (int ni = 0; ni < 8; ni++)
#pragma unroll
            for (int j = 0; j < 4; j++) acc[mi][ni][j] = 0.0f;

    // per-lane A row base byte offsets (4 row groups: +0,+8,+16,+24)
    int base[4];
#pragma unroll
    for (int q = 0; q < 4; q++) {
        int row = warp * 32 + q * 8 + (lane >> 2);
        int nn = row / PXT, rem = row % PXT;
        int py = rem / TX, px = rem % TX;
        base[q] = ((nn * (TY + 2) + py) * (TX + 2) + px) * KCP + (lane & 3) * 4;
    }

    for (int ch = 0; ch < NCH; ch++) {
#pragma unroll
        for (int grp = 0; grp < 2; grp++) {
            const int k0 = grp ? 5 : 0;
            const int kN = grp ? 4 : 5;
            if (grp == 0) {
                // ---- stage A chunk (halo, zero-filled OOB) ----
                for (int u = tid; u < SIN_PIX * 8; u += 256) {
                    int j   = u & 7;
                    int pix = u >> 3;
                    int xx  = pix % (TX + 2);
                    int yy  = (pix / (TX + 2)) % (TY + 2);
                    int nn  = pix / ((TX + 2) * (TY + 2));
                    int gy = ty0 + yy - 1, gx = tx0 + xx - 1;
                    bool ok = (unsigned)gy < (unsigned)H && (unsigned)gx < (unsigned)W;
                    const char* src = ok
                        ? inb + ((((size_t)(n0 + nn) * H + gy) * W + gx) * CIN + ch * 64 + j * 8) * 2
                        : inb;
                    cp16(smem_u32(s_in + pix * KCP + j * 16), src, ok ? 16 : 0);
                }
            }
            // ---- stage weight group ----
            for (int u = tid; u < kN * 512; u += 256) {
                int kl  = u >> 9;
                int rem = u & 511;
                int r = rem >> 3, j = rem & 7;
                const char* src = wqb +
                    (((size_t)((k0 + kl) * NCH + ch) * COUT + oc0 + r) * 64 + j * 8) * 2;
                cp16(smem_u32(s_w + (kl * 64 + r) * KCP + j * 16), src, 16);
            }
            cp_commit_wait();
            __syncthreads();

            // ---- compute this tap group ----
#pragma unroll
            for (int kl = 0; kl < (grp ? 4 : 5); kl++) {
                const int kpos = k0 + kl;
                const int off0 = ((kpos / 3) * (TX + 2) + (kpos % 3)) * KCP;
#pragma unroll
                for (int ks = 0; ks < 4; ks++) {
                    const int off = off0 + ks * 32;
                    unsigned a[2][4];
#pragma unroll
                    for (int mi = 0; mi < 2; mi++) {
                        a[mi][0] = *(const unsigned*)(s_in + base[2 * mi]     + off);
                        a[mi][1] = *(const unsigned*)(s_in + base[2 * mi + 1] + off);
                        a[mi][2] = *(const unsigned*)(s_in + base[2 * mi]     + off + 16);
                        a[mi][3] = *(const unsigned*)(s_in + base[2 * mi + 1] + off + 16);
                    }
                    const char* wb = s_w + (kl * 64 + (lane >> 2)) * KCP + ks * 32 + (lane & 3) * 4;
#pragma unroll
                    for (int ni = 0; ni < 8; ni++) {
                        unsigned b0 = *(const unsigned*)(wb + ni * 8 * KCP);
                        unsigned b1 = *(const unsigned*)(wb + ni * 8 * KCP + 16);
                        mma_bf16(acc[0][ni], a[0], b0, b1);
                        mma_bf16(acc[1][ni], a[1], b0, b1);
                    }
                }
            }
            __syncthreads();
        }
    }

    // ---- epilogue: quantized activation -> bf16 NHWC ----
#pragma unroll
    for (int mi = 0; mi < 2; mi++) {
#pragma unroll
        for (int half = 0; half < 2; half++) {
            int row = warp * 32 + mi * 16 + (lane >> 2) + half * 8;
            int nn = row / PXT, rem = row % PXT;
            int py = rem / TX, px = rem % TX;
            size_t ob = (((size_t)(n0 + nn) * H + ty0 + py) * W + tx0 + px) * COUT + oc0;
#pragma unroll
            for (int ni = 0; ni < 8; ni++) {
                int col = ni * 8 + (lane & 3) * 2;
                float lv[2];
#pragma unroll
                for (int l = 0; l < 2; l++) {
                    float y = acc[mi][ni][half * 2 + l] / 49.0f;
                    float p = y * g[oc0 + col + l] + bb[oc0 + col + l];
                    p = fminf(fmaxf(p, -1.0f), 1.0f);
                    lv[l] = fmaxf(rintf(p * 7.0f), 0.0f);
                }
                *(unsigned*)((char*)out + (ob + col) * 2) = pack_bf16x2(lv[0], lv[1]);
            }
        }
    }
}

// ---------------- pools ----------------
__global__ void pool_bf16(const unsigned* __restrict__ in, unsigned* __restrict__ out,
                          int Wo, int C2, int total) {
    int idx = blockIdx.x * blockDim.x + threadIdx.x;
    if (idx >= total) return;
    int c2 = idx % C2;
    int t = idx / C2;
    int xo = t % Wo; t /= Wo;
    int yo = t % Wo;
    int n = t / Wo;
    int Wi = 2 * Wo;
    const unsigned* p = in + (((size_t)n * Wi + 2 * yo) * Wi + 2 * xo) * C2 + c2;
    __nv_bfloat162 a = *(const __nv_bfloat162*)&p[0];
    __nv_bfloat162 b = *(const __nv_bfloat162*)&p[C2];
    __nv_bfloat162 c = *(const __nv_bfloat162*)&p[(size_t)Wi * C2];
    __nv_bfloat162 d = *(const __nv_bfloat162*)&p[(size_t)Wi * C2 + C2];
    __nv_bfloat162 m = __hmax2(__hmax2(a, b), __hmax2(c, d));
    out[idx] = *(unsigned*)&m;
}
// pool 8->4 on bf16 levels -> packed int8 words for FC1
__global__ void pool3_int8(const unsigned* __restrict__ in, unsigned* __restrict__ out,
                           int total) {
    int idx = blockIdx.x * blockDim.x + threadIdx.x;
    if (idx >= total) return;
    int c4 = idx % 64;
    int px = (idx / 64) % 16;
    int n = idx / 1024;
    int xo = px % 4, yo = px / 4;
    unsigned word = 0;
#pragma unroll
    for (int h = 0; h < 2; h++) {
        int c2 = c4 * 2 + h;
        const unsigned* p = in + (((size_t)n * 8 + 2 * yo) * 8 + 2 * xo) * 128 + c2;
        __nv_bfloat162 a = *(const __nv_bfloat162*)&p[0];
        __nv_bfloat162 b = *(const __nv_bfloat162*)&p[128];
        __nv_bfloat162 c = *(const __nv_bfloat162*)&p[8 * 128];
        __nv_bfloat162 d = *(const __nv_bfloat162*)&p[8 * 128 + 128];
        __nv_bfloat162 m = __hmax2(__hmax2(a, b), __hmax2(c, d));
        int v0 = (int)__low2float(m);
        int v1 = (int)__high2float(m);
        word |= ((unsigned)v0 << (16 * h)) | ((unsigned)v1 << (16 * h + 8));
    }
    out[idx] = word;
}

// ---------------- FC ----------------
__global__ void fc1_kernel(const int* __restrict__ h, const int* __restrict__ w,
                           const float* __restrict__ g, const float* __restrict__ b,
                           unsigned char* __restrict__ out) {
    __shared__ int sa[16][17];
    __shared__ int sw[16][17];
    const int tx = threadIdx.x, ty = threadIdx.y;
    const int n = blockIdx.y * 16 + ty;
    const int o = blockIdx.x * 16 + tx;
    int acc = 0;
    for (int m0 = 0; m0 < 1024; m0 += 16) {
        sa[ty][tx] = h[(blockIdx.y * 16 + ty) * 1024 + m0 + tx];
        sw[ty][tx] = w[(blockIdx.x * 16 + ty) * 1024 + m0 + tx];
        __syncthreads();
#pragma unroll
        for (int mm = 0; mm < 16; mm++) acc = __dp4a(sa[ty][mm], sw[tx][mm], acc);
        __syncthreads();
    }
    float y = (float)acc / 49.0f;
    float p = y * g[o] + b[o];
    p = fminf(fmaxf(p, -1.0f), 1.0f);
    int lev = max((int)rintf(p * 7.0f), 0);
    out[n * 512 + o] = (unsigned char)lev;
}
__global__ void fc2_kernel(const unsigned char* __restrict__ h,
                           const signed char* __restrict__ w,
                           const float* __restrict__ g, const float* __restrict__ b,
                           float* __restrict__ out) {
    const int n = blockIdx.x;
    const int lane = threadIdx.x;
    for (int o = 0; o < 10; o++) {
        int acc = 0;
        for (int k = lane; k < 512; k += 32)
            acc += (int)h[n * 512 + k] * (int)w[o * 512 + k];
#pragma unroll
        for (int off = 16; off > 0; off >>= 1)
            acc += __shfl_xor_sync(0xFFFFFFFFu, acc, off);
        if (lane == 0) {
            float y = (float)acc / 49.0f;
            float p = y * g[o] + b[o];
            p = fminf(fmaxf(p, -1.0f), 1.0f);
            out[n * 10 + o] = (float)((int)rintf(p * 7.0f)) / 7.0f;
        }
    }
}

// ---------------- launch ----------------
extern "C" void kernel_launch(void* const* d_in, const int* in_sizes, int n_in,
                              void* d_out, int out_size) {
    const float* x = (const float*)d_in[0];
    const float *w1 = (const float*)d_in[1], *g1 = (const float*)d_in[2], *b1 = (const float*)d_in[3];
    const float *w2 = (const float*)d_in[4], *g2 = (const float*)d_in[5], *b2 = (const float*)d_in[6];
    const float *w3 = (const float*)d_in[7], *g3 = (const float*)d_in[8], *b3 = (const float*)d_in[9];
    const float *w4 = (const float*)d_in[10], *g4 = (const float*)d_in[11], *b4 = (const float*)d_in[12];
    const float *w5 = (const float*)d_in[13], *g5 = (const float*)d_in[14], *b5 = (const float*)d_in[15];
    const float *w6 = (const float*)d_in[16], *g6 = (const float*)d_in[17], *b6 = (const float*)d_in[18];
    const float *wf1 = (const float*)d_in[19], *gf1 = (const float*)d_in[20], *bf1 = (const float*)d_in[21];
    const float *wf2 = (const float*)d_in[22], *gf2 = (const float*)d_in[23], *bf2 = (const float*)d_in[24];

    void *bufA, *bufB, *qw1, *w2p, *w3p, *w4p, *w5p, *w6p, *wf1p, *wf2p, *fc1o;
    cudaGetSymbolAddress(&bufA, g_bufA);
    cudaGetSymbolAddress(&bufB, g_bufB);
    cudaGetSymbolAddress(&qw1, g_qw1);
    cudaGetSymbolAddress(&w2p, g_wb2);
    cudaGetSymbolAddress(&w3p, g_wb3);
    cudaGetSymbolAddress(&w4p, g_wb4);
    cudaGetSymbolAddress(&w5p, g_wb5);
    cudaGetSymbolAddress(&w6p, g_wb6);
    cudaGetSymbolAddress(&wf1p, g_wf1);
    cudaGetSymbolAddress(&wf2p, g_wf2);
    cudaGetSymbolAddress(&fc1o, g_fc1);

    auto k2 = conv_hmma<32, 32, 16, 16, 1, 64, 64>;
    auto k3 = conv_hmma<16, 16, 16, 16, 1, 64, 128>;
    auto k4 = conv_hmma<16, 16, 16, 16, 1, 128, 128>;
    auto k5 = conv_hmma<8, 8, 8, 8, 4, 128, 256>;
    auto k6 = conv_hmma<8, 8, 8, 8, 4, 256, 256>;
    const int smA = (1 * 18 * 18) * 144 + 5 * 64 * 144;   // 46656 + 46080 = 92736
    const int smB = (4 * 10 * 10) * 144 + 5 * 64 * 144;   // 57600 + 46080 = 103680
    cudaFuncSetAttribute(k2, cudaFuncAttributeMaxDynamicSharedMemorySize, smA);
    cudaFuncSetAttribute(k3, cudaFuncAttributeMaxDynamicSharedMemorySize, smA);
    cudaFuncSetAttribute(k4, cudaFuncAttributeMaxDynamicSharedMemorySize, smA);
    cudaFuncSetAttribute(k5, cudaFuncAttributeMaxDynamicSharedMemorySize, smB);
    cudaFuncSetAttribute(k6, cudaFuncAttributeMaxDynamicSharedMemorySize, smB);

    // Launch order arranged so ncu (-s 5 -c 1) captures launch #6 = conv L2.
    quant_w1_k<<<7, 256>>>(w1, (float*)qw1, 1728);                                   // 1
    pack_convw_bf16<<<(64 * 9 * 64 + 255) / 256, 256>>>(w2, (__nv_bfloat16*)w2p, 64, 64); // 2
    pack_fc1_k<<<(512 * 1024 + 255) / 256, 256>>>(wf1, (int*)wf1p);                  // 3
    pack_fc2_k<<<20, 256>>>(wf2, (signed char*)wf2p);                                // 4
    conv1_kernel<<<dim3(4, 512), 1024>>>(x, (const float*)qw1, g1, b1, (__nv_bfloat16*)bufA); // 5
    // L2: 64->64 @32, A->B                                                          // 6 (profiled)
    k2<<<dim3(1, 4, 512), 256, smA>>>((const __nv_bfloat16*)bufA, (const __nv_bfloat16*)w2p,
                                      g2, b2, (__nv_bfloat16*)bufB);
    pack_convw_bf16<<<(128 * 9 * 64 + 255) / 256, 256>>>(w3, (__nv_bfloat16*)w3p, 128, 64);
    pack_convw_bf16<<<(128 * 9 * 128 + 255) / 256, 256>>>(w4, (__nv_bfloat16*)w4p, 128, 128);
    pack_convw_bf16<<<(256 * 9 * 128 + 255) / 256, 256>>>(w5, (__nv_bfloat16*)w5p, 256, 128);
    pack_convw_bf16<<<(256 * 9 * 256 + 255) / 256, 256>>>(w6, (__nv_bfloat16*)w6p, 256, 256);
    {   // pool 32->16 (C2=32): B->A
        int total = 512 * 16 * 16 * 32;
        pool_bf16<<<(total + 255) / 256, 256>>>((const unsigned*)bufB, (unsigned*)bufA, 16, 32, total);
    }
    // L3: 64->128 @16, A->B
    k3<<<dim3(2, 1, 512), 256, smA>>>((const __nv_bfloat16*)bufA, (const __nv_bfloat16*)w3p,
                                      g3, b3, (__nv_bfloat16*)bufB);
    // L4: 128->128 @16, B->A
    k4<<<dim3(2, 1, 512), 256, smA>>>((const __nv_bfloat16*)bufB, (const __nv_bfloat16*)w4p,
                                      g4, b4, (__nv_bfloat16*)bufA);
    {   // pool 16->8 (C2=64): A->B
        int total = 512 * 8 * 8 * 64;
        pool_bf16<<<(total + 255) / 256, 256>>>((const unsigned*)bufA, (unsigned*)bufB, 8, 64, total);
    }
    // L5: 128->256 @8, B->A
    k5<<<dim3(4, 1, 128), 256, smB>>>((const __nv_bfloat16*)bufB, (const __nv_bfloat16*)w5p,
                                      g5, b5, (__nv_bfloat16*)bufA);
    // L6: 256->256 @8, A->B
    k6<<<dim3(4, 1, 128), 256, smB>>>((const __nv_bfloat16*)bufA, (const __nv_bfloat16*)w6p,
                                      g6, b6, (__nv_bfloat16*)bufB);
    {   // pool 8->4 -> packed int8 words: B->A
        int total = 512 * 16 * 64;
        pool3_int8<<<(total + 255) / 256, 256>>>((const unsigned*)bufB, (unsigned*)bufA, total);
    }

    fc1_kernel<<<dim3(32, 32), dim3(16, 16)>>>((const int*)bufA, (const int*)wf1p, gf1, bf1,
                                               (unsigned char*)fc1o);
    fc2_kernel<<<512, 32>>>((const unsigned char*)fc1o, (const signed char*)wf2p, gf2, bf2,
                            (float*)d_out);
}

// round 8
// speedup vs baseline: 3.1708x; 1.0200x over previous
#include <cuda_runtime.h>
#include <cuda_bf16.h>
#include <cstdint>

// ============================================================================
// IntegerCifar10Net R8: bf16 HMMA convs + ldmatrix fragment loads (issue-count
// cut 45%), occupancy-2, cp.async staging. Exact integer arithmetic.
// ============================================================================

__device__ __forceinline__ int qlev(float w) {
    w = fminf(fmaxf(w, -1.0f), 1.0f);
    return (int)rintf(w * 7.0f);
}
__device__ __forceinline__ unsigned pack_bf16x2(float lo, float hi) {
    unsigned r;
    asm("cvt.rn.bf16x2.f32 %0, %1, %2;" : "=r"(r) : "f"(hi), "f"(lo));
    return r;
}
__device__ __forceinline__ unsigned smem_u32(const void* p) {
    return (unsigned)__cvta_generic_to_shared(p);
}
__device__ __forceinline__ void cp16(unsigned dst, const void* src, int szvalid) {
    asm volatile("cp.async.cg.shared.global [%0], [%1], 16, %2;"
                 :: "r"(dst), "l"(src), "r"(szvalid) : "memory");
}
__device__ __forceinline__ void cp_commit_wait() {
    asm volatile("cp.async.commit_group;" ::: "memory");
    asm volatile("cp.async.wait_group 0;" ::: "memory");
}
__device__ __forceinline__ void ldsm4(unsigned* r, unsigned addr) {
    asm volatile("ldmatrix.sync.aligned.m8n8.x4.shared.b16 {%0,%1,%2,%3}, [%4];"
                 : "=r"(r[0]), "=r"(r[1]), "=r"(r[2]), "=r"(r[3]) : "r"(addr));
}

// ---------------- scratch ----------------
__device__ __nv_bfloat16 g_bufA[512 * 32 * 32 * 64];
__device__ __nv_bfloat16 g_bufB[512 * 32 * 32 * 64];
__device__ float         g_qw1[64 * 3 * 9];
__device__ __nv_bfloat16 g_wb2[9 * 1 * 64 * 64];
__device__ __nv_bfloat16 g_wb3[9 * 1 * 128 * 64];
__device__ __nv_bfloat16 g_wb4[9 * 2 * 128 * 64];
__device__ __nv_bfloat16 g_wb5[9 * 2 * 256 * 64];
__device__ __nv_bfloat16 g_wb6[9 * 4 * 256 * 64];
__device__ int           g_wf1[512 * 1024];
__device__ signed char   g_wf2[10 * 512];
__device__ unsigned char g_fc1[512 * 512];

// ---------------- weight prep ----------------
__global__ void quant_w1_k(const float* __restrict__ w, float* __restrict__ qw, int n) {
    int i = blockIdx.x * blockDim.x + threadIdx.x;
    if (i < n) qw[i] = (float)qlev(w[i]) / 7.0f;
}
// OIHW float -> bf16 [kpos][ch][oc][64]
__global__ void pack_convw_bf16(const float* __restrict__ w, __nv_bfloat16* __restrict__ out,
                                int COUT, int CIN) {
    int idx = blockIdx.x * blockDim.x + threadIdx.x;
    int NCH = CIN / 64;
    if (idx >= COUT * 9 * CIN) return;
    int j = idx % 64;
    int t = idx / 64;
    int oc = t % COUT; t /= COUT;
    int ch = t % NCH;
    int kpos = t / NCH;
    out[idx] = __float2bfloat16((float)qlev(w[(oc * CIN + ch * 64 + j) * 9 + kpos]));
}
__global__ void pack_fc1_k(const float* __restrict__ w, int* __restrict__ out) {
    int idx = blockIdx.x * blockDim.x + threadIdx.x;
    if (idx >= 512 * 1024) return;
    int wi = idx % 1024, o = idx / 1024;
    int px = wi / 64, c4 = wi % 64;
    unsigned word = 0;
#pragma unroll
    for (int l = 0; l < 4; l++) {
        int k = (4 * c4 + l) * 16 + px;
        word |= (unsigned)(qlev(w[o * 4096 + k]) & 0xFF) << (8 * l);
    }
    out[idx] = (int)word;
}
__global__ void pack_fc2_k(const float* __restrict__ w, signed char* __restrict__ out) {
    int idx = blockIdx.x * blockDim.x + threadIdx.x;
    if (idx < 10 * 512) out[idx] = (signed char)qlev(w[idx]);
}

// ---------------- conv1: fp32 NCHW -> bf16 NHWC levels ----------------
__global__ void __launch_bounds__(1024)
conv1_kernel(const float* __restrict__ x, const float* __restrict__ qw,
             const float* __restrict__ g, const float* __restrict__ b,
             __nv_bfloat16* __restrict__ out) {
    __shared__ float s_in[3][34][34];
    __shared__ float s_w[16][27];
    const int tid = threadIdx.x;
    const int oy = tid / 32, ox = tid % 32;
    const int n = blockIdx.y;
    const int oc0 = blockIdx.x * 16;
    for (int i = tid; i < 3 * 34 * 34; i += 1024) {
        int t = i;
        int xx = t % 34; t /= 34;
        int yy = t % 34; t /= 34;
        int c = t;
        int yi = yy - 1, xi = xx - 1;
        float v = 0.0f;
        if ((unsigned)yi < 32u && (unsigned)xi < 32u)
            v = x[((n * 3 + c) * 32 + yi) * 32 + xi];
        s_in[c][yy][xx] = v;
    }
    for (int i = tid; i < 16 * 27; i += 1024)
        s_w[i / 27][i % 27] = qw[(oc0 + i / 27) * 27 + i % 27];
    __syncthreads();
    float acc[16];
#pragma unroll
    for (int o = 0; o < 16; o++) acc[o] = 0.0f;
#pragma unroll
    for (int c = 0; c < 3; c++) {
        float wv[9];
#pragma unroll
        for (int ky = 0; ky < 3; ky++)
#pragma unroll
            for (int kx = 0; kx < 3; kx++)
                wv[ky * 3 + kx] = s_in[c][oy + ky][ox + kx];
#pragma unroll
        for (int o = 0; o < 16; o++) {
            float a = acc[o];
#pragma unroll
            for (int k = 0; k < 9; k++) a = fmaf(wv[k], s_w[o][c * 9 + k], a);
            acc[o] = a;
        }
    }
    unsigned* ob = (unsigned*)(out + ((size_t)(n * 1024) + oy * 32 + ox) * 64 + oc0);
#pragma unroll
    for (int j = 0; j < 8; j++) {
        float lv[2];
#pragma unroll
        for (int l = 0; l < 2; l++) {
            int o = j * 2 + l;
            float p = acc[o] * g[oc0 + o] + b[oc0 + o];
            p = fminf(fmaxf(p, -1.0f), 1.0f);
            lv[l] = fmaxf(rintf(p * 7.0f), 0.0f);
        }
        ob[j] = pack_bf16x2(lv[0], lv[1]);
    }
}

// ---------------- bf16 HMMA conv (ldmatrix + occupancy 2) ----------------
__device__ __forceinline__ void mma_bf16(float* d, const unsigned* a, unsigned b0, unsigned b1) {
    asm volatile(
        "mma.sync.aligned.m16n8k16.row.col.f32.bf16.bf16.f32 "
        "{%0,%1,%2,%3},{%4,%5,%6,%7},{%8,%9},{%0,%1,%2,%3};"
        : "+f"(d[0]), "+f"(d[1]), "+f"(d[2]), "+f"(d[3])
        : "r"(a[0]), "r"(a[1]), "r"(a[2]), "r"(a[3]), "r"(b0), "r"(b1));
}

// act [n][H][W][CIN] bf16 ; weight [kpos][ch][oc][64] bf16
template <int H, int W, int TY, int TX, int NB, int CIN, int COUT>
__global__ void __launch_bounds__(256, 2)
conv_hmma(const __nv_bfloat16* __restrict__ in, const __nv_bfloat16* __restrict__ wq,
          const float* __restrict__ g, const float* __restrict__ bb,
          __nv_bfloat16* __restrict__ out) {
    constexpr int NCH = CIN / 64;
    constexpr int KCP = 144;                 // 128B chunk + 16B pad
    constexpr int PXT = TY * TX;
    constexpr int SIN_PIX = NB * (TY + 2) * (TX + 2);

    extern __shared__ char smem[];
    char* s_in = smem;                       // SIN_PIX * KCP
    char* s_w  = smem + SIN_PIX * KCP;       // 5 * 64 * KCP (max group)

    const int tid  = threadIdx.x;
    const int warp = tid >> 5, lane = tid & 31;
    const int oc0  = blockIdx.x * 64;
    const int ty0  = (blockIdx.y / (W / TX)) * TY;
    const int tx0  = (blockIdx.y % (W / TX)) * TX;
    const int n0   = blockIdx.z * NB;
    const char* inb = (const char*)in;
    const char* wqb = (const char*)wq;

    float acc[2][8][4];
#pragma unroll
    for (int mi = 0; mi < 2; mi++)
#pragma unroll
        for (int ni = 0; ni < 8; ni++)
#pragma unroll
            for (int j = 0; j < 4; j++) acc[mi][ni][j] = 0.0f;

    // ldmatrix per-lane base addresses
    unsigned Abase[2];
#pragma unroll
    for (int mi = 0; mi < 2; mi++) {
        int row_local = ((lane >> 3) & 1) * 8 + (lane & 7);
        int p = warp * 32 + mi * 16 + row_local;
        int nn = p / PXT, rem = p % PXT;
        int py = rem / TX, px = rem % TX;
        Abase[mi] = smem_u32(s_in) + ((nn * (TY + 2) + py) * (TX + 2) + px) * KCP
                    + (lane >> 4) * 16;
    }
    const unsigned Bbase = smem_u32(s_w) + ((lane & 7) + (lane >> 4) * 8) * KCP
                           + ((lane >> 3) & 1) * 16;

    for (int ch = 0; ch < NCH; ch++) {
#pragma unroll
        for (int grp = 0; grp < 2; grp++) {
            const int k0 = grp ? 5 : 0;
            const int kN = grp ? 4 : 5;
            if (grp == 0) {
                for (int u = tid; u < SIN_PIX * 8; u += 256) {
                    int j   = u & 7;
                    int pix = u >> 3;
                    int xx  = pix % (TX + 2);
                    int yy  = (pix / (TX + 2)) % (TY + 2);
                    int nn  = pix / ((TX + 2) * (TY + 2));
                    int gy = ty0 + yy - 1, gx = tx0 + xx - 1;
                    bool ok = (unsigned)gy < (unsigned)H && (unsigned)gx < (unsigned)W;
                    const char* src = ok
                        ? inb + ((((size_t)(n0 + nn) * H + gy) * W + gx) * CIN + ch * 64 + j * 8) * 2
                        : inb;
                    cp16(smem_u32(s_in + pix * KCP + j * 16), src, ok ? 16 : 0);
                }
            }
            for (int u = tid; u < kN * 512; u += 256) {
                int kl  = u >> 9;
                int rem = u & 511;
                int r = rem >> 3, j = rem & 7;
                const char* src = wqb +
                    (((size_t)((k0 + kl) * NCH + ch) * COUT + oc0 + r) * 64 + j * 8) * 2;
                cp16(smem_u32(s_w + (kl * 64 + r) * KCP + j * 16), src, 16);
            }
            cp_commit_wait();
            __syncthreads();

#pragma unroll
            for (int kl = 0; kl < (grp ? 4 : 5); kl++) {
                const int kpos = k0 + kl;
                const int off0 = ((kpos / 3) * (TX + 2) + (kpos % 3)) * KCP;
#pragma unroll
                for (int ks = 0; ks < 4; ks++) {
                    const int off = off0 + ks * 32;
                    unsigned a0[4], a1[4];
                    ldsm4(a0, Abase[0] + off);
                    ldsm4(a1, Abase[1] + off);
#pragma unroll
                    for (int np = 0; np < 4; np++) {
                        unsigned b[4];
                        ldsm4(b, Bbase + (kl * 64 + np * 16) * KCP + ks * 32);
                        mma_bf16(acc[0][2 * np],     a0, b[0], b[1]);
                        mma_bf16(acc[0][2 * np + 1], a0, b[2], b[3]);
                        mma_bf16(acc[1][2 * np],     a1, b[0], b[1]);
                        mma_bf16(acc[1][2 * np + 1], a1, b[2], b[3]);
                    }
                }
            }
            __syncthreads();
        }
    }

    // ---- epilogue: quantized activation -> bf16 NHWC ----
#pragma unroll
    for (int mi = 0; mi < 2; mi++) {
#pragma unroll
        for (int half = 0; half < 2; half++) {
            int row = warp * 32 + mi * 16 + (lane >> 2) + half * 8;
            int nn = row / PXT, rem = row % PXT;
            int py = rem / TX, px = rem % TX;
            size_t ob = (((size_t)(n0 + nn) * H + ty0 + py) * W + tx0 + px) * COUT + oc0;
#pragma unroll
            for (int ni = 0; ni < 8; ni++) {
                int col = ni * 8 + (lane & 3) * 2;
                float lv[2];
#pragma unroll
                for (int l = 0; l < 2; l++) {
                    float y = acc[mi][ni][half * 2 + l] / 49.0f;
                    float p = y * g[oc0 + col + l] + bb[oc0 + col + l];
                    p = fminf(fmaxf(p, -1.0f), 1.0f);
                    lv[l] = fmaxf(rintf(p * 7.0f), 0.0f);
                }
                *(unsigned*)((char*)out + (ob + col) * 2) = pack_bf16x2(lv[0], lv[1]);
            }
        }
    }
}

// ---------------- pools ----------------
__global__ void pool_bf16(const unsigned* __restrict__ in, unsigned* __restrict__ out,
                          int Wo, int C2, int total) {
    int idx = blockIdx.x * blockDim.x + threadIdx.x;
    if (idx >= total) return;
    int c2 = idx % C2;
    int t = idx / C2;
    int xo = t % Wo; t /= Wo;
    int yo = t % Wo;
    int n = t / Wo;
    int Wi = 2 * Wo;
    const unsigned* p = in + (((size_t)n * Wi + 2 * yo) * Wi + 2 * xo) * C2 + c2;
    __nv_bfloat162 a = *(const __nv_bfloat162*)&p[0];
    __nv_bfloat162 b = *(const __nv_bfloat162*)&p[C2];
    __nv_bfloat162 c = *(const __nv_bfloat162*)&p[(size_t)Wi * C2];
    __nv_bfloat162 d = *(const __nv_bfloat162*)&p[(size_t)Wi * C2 + C2];
    __nv_bfloat162 m = __hmax2(__hmax2(a, b), __hmax2(c, d));
    out[idx] = *(unsigned*)&m;
}
__global__ void pool3_int8(const unsigned* __restrict__ in, unsigned* __restrict__ out,
                           int total) {
    int idx = blockIdx.x * blockDim.x + threadIdx.x;
    if (idx >= total) return;
    int c4 = idx % 64;
    int px = (idx / 64) % 16;
    int n = idx / 1024;
    int xo = px % 4, yo = px / 4;
    unsigned word = 0;
#pragma unroll
    for (int h = 0; h < 2; h++) {
        int c2 = c4 * 2 + h;
        const unsigned* p = in + (((size_t)n * 8 + 2 * yo) * 8 + 2 * xo) * 128 + c2;
        __nv_bfloat162 a = *(const __nv_bfloat162*)&p[0];
        __nv_bfloat162 b = *(const __nv_bfloat162*)&p[128];
        __nv_bfloat162 c = *(const __nv_bfloat162*)&p[8 * 128];
        __nv_bfloat162 d = *(const __nv_bfloat162*)&p[8 * 128 + 128];
        __nv_bfloat162 m = __hmax2(__hmax2(a, b), __hmax2(c, d));
        int v0 = (int)__low2float(m);
        int v1 = (int)__high2float(m);
        word |= ((unsigned)v0 << (16 * h)) | ((unsigned)v1 << (16 * h + 8));
    }
    out[idx] = word;
}

// ---------------- FC ----------------
__global__ void fc1_kernel(const int* __restrict__ h, const int* __restrict__ w,
                           const float* __restrict__ g, const float* __restrict__ b,
                           unsigned char* __restrict__ out) {
    __shared__ int sa[16][17];
    __shared__ int sw[16][17];
    const int tx = threadIdx.x, ty = threadIdx.y;
    const int n = blockIdx.y * 16 + ty;
    const int o = blockIdx.x * 16 + tx;
    int acc = 0;
    for (int m0 = 0; m0 < 1024; m0 += 16) {
        sa[ty][tx] = h[(blockIdx.y * 16 + ty) * 1024 + m0 + tx];
        sw[ty][tx] = w[(blockIdx.x * 16 + ty) * 1024 + m0 + tx];
        __syncthreads();
#pragma unroll
        for (int mm = 0; mm < 16; mm++) acc = __dp4a(sa[ty][mm], sw[tx][mm], acc);
        __syncthreads();
    }
    float y = (float)acc / 49.0f;
    float p = y * g[o] + b[o];
    p = fminf(fmaxf(p, -1.0f), 1.0f);
    int lev = max((int)rintf(p * 7.0f), 0);
    out[n * 512 + o] = (unsigned char)lev;
}
__global__ void fc2_kernel(const unsigned char* __restrict__ h,
                           const signed char* __restrict__ w,
                           const float* __restrict__ g, const float* __restrict__ b,
                           float* __restrict__ out) {
    const int n = blockIdx.x;
    const int lane = threadIdx.x;
    for (int o = 0; o < 10; o++) {
        int acc = 0;
        for (int k = lane; k < 512; k += 32)
            acc += (int)h[n * 512 + k] * (int)w[o * 512 + k];
#pragma unroll
        for (int off = 16; off > 0; off >>= 1)
            acc += __shfl_xor_sync(0xFFFFFFFFu, acc, off);
        if (lane == 0) {
            float y = (float)acc / 49.0f;
            float p = y * g[o] + b[o];
            p = fminf(fmaxf(p, -1.0f), 1.0f);
            out[n * 10 + o] = (float)((int)rintf(p * 7.0f)) / 7.0f;
        }
    }
}

// ---------------- launch ----------------
extern "C" void kernel_launch(void* const* d_in, const int* in_sizes, int n_in,
                              void* d_out, int out_size) {
    const float* x = (const float*)d_in[0];
    const float *w1 = (const float*)d_in[1], *g1 = (const float*)d_in[2], *b1 = (const float*)d_in[3];
    const float *w2 = (const float*)d_in[4], *g2 = (const float*)d_in[5], *b2 = (const float*)d_in[6];
    const float *w3 = (const float*)d_in[7], *g3 = (const float*)d_in[8], *b3 = (const float*)d_in[9];
    const float *w4 = (const float*)d_in[10], *g4 = (const float*)d_in[11], *b4 = (const float*)d_in[12];
    const float *w5 = (const float*)d_in[13], *g5 = (const float*)d_in[14], *b5 = (const float*)d_in[15];
    const float *w6 = (const float*)d_in[16], *g6 = (const float*)d_in[17], *b6 = (const float*)d_in[18];
    const float *wf1 = (const float*)d_in[19], *gf1 = (const float*)d_in[20], *bf1 = (const float*)d_in[21];
    const float *wf2 = (const float*)d_in[22], *gf2 = (const float*)d_in[23], *bf2 = (const float*)d_in[24];

    void *bufA, *bufB, *qw1, *w2p, *w3p, *w4p, *w5p, *w6p, *wf1p, *wf2p, *fc1o;
    cudaGetSymbolAddress(&bufA, g_bufA);
    cudaGetSymbolAddress(&bufB, g_bufB);
    cudaGetSymbolAddress(&qw1, g_qw1);
    cudaGetSymbolAddress(&w2p, g_wb2);
    cudaGetSymbolAddress(&w3p, g_wb3);
    cudaGetSymbolAddress(&w4p, g_wb4);
    cudaGetSymbolAddress(&w5p, g_wb5);
    cudaGetSymbolAddress(&w6p, g_wb6);
    cudaGetSymbolAddress(&wf1p, g_wf1);
    cudaGetSymbolAddress(&wf2p, g_wf2);
    cudaGetSymbolAddress(&fc1o, g_fc1);

    auto k2 = conv_hmma<32, 32, 16, 16, 1, 64, 64>;
    auto k3 = conv_hmma<16, 16, 16, 16, 1, 64, 128>;
    auto k4 = conv_hmma<16, 16, 16, 16, 1, 128, 128>;
    auto k5 = conv_hmma<8, 8, 8, 8, 4, 128, 256>;
    auto k6 = conv_hmma<8, 8, 8, 8, 4, 256, 256>;
    const int smA = (1 * 18 * 18) * 144 + 5 * 64 * 144;   // 92736
    const int smB = (4 * 10 * 10) * 144 + 5 * 64 * 144;   // 103680
    cudaFuncSetAttribute(k2, cudaFuncAttributeMaxDynamicSharedMemorySize, smA);
    cudaFuncSetAttribute(k3, cudaFuncAttributeMaxDynamicSharedMemorySize, smA);
    cudaFuncSetAttribute(k4, cudaFuncAttributeMaxDynamicSharedMemorySize, smA);
    cudaFuncSetAttribute(k5, cudaFuncAttributeMaxDynamicSharedMemorySize, smB);
    cudaFuncSetAttribute(k6, cudaFuncAttributeMaxDynamicSharedMemorySize, smB);

    quant_w1_k<<<7, 256>>>(w1, (float*)qw1, 1728);
    pack_convw_bf16<<<(64 * 9 * 64 + 255) / 256, 256>>>(w2, (__nv_bfloat16*)w2p, 64, 64);
    conv1_kernel<<<dim3(4, 512), 1024>>>(x, (const float*)qw1, g1, b1, (__nv_bfloat16*)bufA);
    // L2: 64->64 @32, A->B
    k2<<<dim3(1, 4, 512), 256, smA>>>((const __nv_bfloat16*)bufA, (const __nv_bfloat16*)w2p,
                                      g2, b2, (__nv_bfloat16*)bufB);
    pack_convw_bf16<<<(128 * 9 * 64 + 255) / 256, 256>>>(w3, (__nv_bfloat16*)w3p, 128, 64);
    pack_convw_bf16<<<(128 * 9 * 128 + 255) / 256, 256>>>(w4, (__nv_bfloat16*)w4p, 128, 128);
    pack_convw_bf16<<<(256 * 9 * 128 + 255) / 256, 256>>>(w5, (__nv_bfloat16*)w5p, 256, 128);
    pack_convw_bf16<<<(256 * 9 * 256 + 255) / 256, 256>>>(w6, (__nv_bfloat16*)w6p, 256, 256);
    pack_fc1_k<<<(512 * 1024 + 255) / 256, 256>>>(wf1, (int*)wf1p);
    pack_fc2_k<<<20, 256>>>(wf2, (signed char*)wf2p);
    {   // pool 32->16 (C2=32): B->A
        int total = 512 * 16 * 16 * 32;
        pool_bf16<<<(total + 255) / 256, 256>>>((const unsigned*)bufB, (unsigned*)bufA, 16, 32, total);
    }
    // L3: 64->128 @16, A->B
    k3<<<dim3(2, 1, 512), 256, smA>>>((const __nv_bfloat16*)bufA, (const __nv_bfloat16*)w3p,
                                      g3, b3, (__nv_bfloat16*)bufB);
    // L4: 128->128 @16, B->A
    k4<<<dim3(2, 1, 512), 256, smA>>>((const __nv_bfloat16*)bufB, (const __nv_bfloat16*)w4p,
                                      g4, b4, (__nv_bfloat16*)bufA);
    {   // pool 16->8 (C2=64): A->B
        int total = 512 * 8 * 8 * 64;
        pool_bf16<<<(total + 255) / 256, 256>>>((const unsigned*)bufA, (unsigned*)bufB, 8, 64, total);
    }
    // L5: 128->256 @8, B->A
    k5<<<dim3(4, 1, 128), 256, smB>>>((const __nv_bfloat16*)bufB, (const __nv_bfloat16*)w5p,
                                      g5, b5, (__nv_bfloat16*)bufA);
    // L6: 256->256 @8, A->B
    k6<<<dim3(4, 1, 128), 256, smB>>>((const __nv_bfloat16*)bufA, (const __nv_bfloat16*)w6p,
                                      g6, b6, (__nv_bfloat16*)bufB);
    {   // pool 8->4 -> packed int8 words: B->A
        int total = 512 * 16 * 64;
        pool3_int8<<<(total + 255) / 256, 256>>>((const unsigned*)bufB, (unsigned*)bufA, total);
    }

    fc1_kernel<<<dim3(32, 32), dim3(16, 16)>>>((const int*)bufA, (const int*)wf1p, gf1, bf1,
                                               (unsigned char*)fc1o);
    fc2_kernel<<<512, 32>>>((const unsigned char*)fc1o, (const signed char*)wf2p, gf2, bf2,
                            (float*)d_out);
}